// round 12
// baseline (speedup 1.0000x reference)
#include <cuda_runtime.h>
#include <cuda_fp16.h>
#include <math.h>
#include <stdint.h>

#define N_NODES 100000
#define N_EDGES 1000000
#define AST 40   // A/W tile half stride (ldmatrix conflict-free, 16B-aligned rows)
#define CST 72   // Cs half stride

// ---------------- device scratch ----------------
__device__ int   g_is64;
__device__ __align__(16) int   g_degi[N_NODES];
__device__ __align__(16) float g_dis[N_NODES];
__device__ __align__(16) int   g_rowptr[N_NODES + 1];
__device__ __align__(16) int   g_fill[N_NODES];
__device__ __align__(16) int2  g_cw[N_EDGES];
__device__ __align__(16) int   g_part[512];
__device__ __align__(16) float g_bnsum[128];
__device__ __align__(16) float g_bnsq[128];
__device__ __align__(16) float g_b1f[64];     // folded bias: b1 + t @ W1
__device__ __align__(16) __half g_x16[N_NODES * 128];
__device__ __align__(16) __half g_a16[N_NODES * 128];
__device__ __align__(16) float  g_xp [N_NODES * 128];   // L3 x-branch partial (fp32)
// unified activation buffer: cols [0,64)=h [64,128)=Ah [128,192)=A2h [192,256)=A3h
__device__ __align__(16) __half g_act[N_NODES * 256];
// pre-split transposed weights: hi/lo fp16, [N][K] k-major
// W1(scaled)=0(8192) T1=8192 W2=24576 T2=28672 W3=45056 W4=69632
__device__ __align__(16) __half g_wthi[77824];
__device__ __align__(16) __half g_wtlo[77824];

// ---------------- helpers ----------------
__device__ __forceinline__ float gelu_f(float v) {
    return 0.5f * v * (1.0f + erff(v * 0.70710678118654752440f));
}

__device__ __forceinline__ void mmaf16(float d[4], const uint32_t a[4],
                                       uint32_t b0, uint32_t b1) {
    asm volatile(
        "mma.sync.aligned.m16n8k16.row.col.f32.f16.f16.f32 "
        "{%0,%1,%2,%3}, {%4,%5,%6,%7}, {%8,%9}, {%0,%1,%2,%3};"
        : "+f"(d[0]), "+f"(d[1]), "+f"(d[2]), "+f"(d[3])
        : "r"(a[0]), "r"(a[1]), "r"(a[2]), "r"(a[3]), "r"(b0), "r"(b1));
}

__device__ __forceinline__ void ldsm_x4(uint32_t r[4], uint32_t a) {
    asm volatile("ldmatrix.sync.aligned.m8n8.x4.shared.b16 {%0,%1,%2,%3}, [%4];"
        : "=r"(r[0]), "=r"(r[1]), "=r"(r[2]), "=r"(r[3]) : "r"(a));
}

__device__ __forceinline__ uint32_t smaddr(const void* p) {
    return (uint32_t)__cvta_generic_to_shared(p);
}

__device__ __forceinline__ void cpa16(uint32_t dst, const void* src, bool p) {
    int sz = p ? 16 : 0;
    asm volatile("cp.async.cg.shared.global [%0], [%1], 16, %2;"
        :: "r"(dst), "l"(src), "r"(sz));
}
__device__ __forceinline__ void cpcommit() { asm volatile("cp.async.commit_group;"); }
__device__ __forceinline__ void cpwait1()  { asm volatile("cp.async.wait_group 1;"); }
__device__ __forceinline__ void cpwait0()  { asm volatile("cp.async.wait_group 0;"); }

// one 32-K step of mma with ldmatrix fragments; WLO = use lo-half of W split
template <int NT, bool WLO>
__device__ __forceinline__ void mma_tile_l(
    float d[2][NT][4], uint32_t Ab_addr, int astr,
    uint32_t Wh_addr, uint32_t Wl_addr,
    int Rm, int Cn, int lane) {
#pragma unroll
    for (int ks = 0; ks < 2; ks++) {
        int kk = ks * 16;
        uint32_t a[2][4];
#pragma unroll
        for (int mt = 0; mt < 2; mt++) {
            int row = Rm + 16 * mt + (lane & 15);
            int kof = kk + 8 * (lane >> 4);
            ldsm_x4(a[mt], Ab_addr + ((row * astr + kof) << 1));
        }
        uint32_t bh[NT / 2][4], bl[NT / 2][4];
#pragma unroll
        for (int q = 0; q < NT / 2; q++) {
            int row = Cn + q * 16 + (lane & 7) + ((lane >> 4) << 3);
            int kof = kk + 8 * ((lane >> 3) & 1);
            uint32_t off = (uint32_t)((row * AST + kof) << 1);
            ldsm_x4(bh[q], Wh_addr + off);
            if (WLO) ldsm_x4(bl[q], Wl_addr + off);
        }
#pragma unroll
        for (int q = 0; q < NT / 2; q++) {
#pragma unroll
            for (int h = 0; h < 2; h++) {
                int nt = q * 2 + h;
#pragma unroll
                for (int mt = 0; mt < 2; mt++) {
                    mmaf16(d[mt][nt], a[mt], bh[q][2 * h], bh[q][2 * h + 1]);
                    if (WLO) mmaf16(d[mt][nt], a[mt], bl[q][2 * h], bl[q][2 * h + 1]);
                }
            }
        }
    }
}

// A tile cp.async: 128 rows x 32 halfs from contiguous fp16 [.][KX]
__device__ __forceinline__ void loadA_cp(uint32_t asbuf, const __half* Ag,
                                         int m0, int KX, int k0, int tid) {
#pragma unroll
    for (int i = 0; i < 2; i++) {
        int idx = i * 256 + tid;
        int r = idx >> 2;
        int c8 = (idx & 3) * 8;
        int gr = m0 + r;
        bool p = gr < N_NODES;
        int rr = p ? gr : (N_NODES - 1);
        cpa16(asbuf + r * (AST * 2) + c8 * 2,
              Ag + (size_t)rr * KX + k0 + c8, p);
    }
}

// W tile cp.async: N2 rows x 32 halfs from [N2][Wstride] (hi, and lo if WLO)
template <int N2, bool WLO>
__device__ __forceinline__ void loadW_cp(uint32_t wh, uint32_t wl,
                                         const __half* Whg, const __half* Wlg,
                                         int Wstride, int k0, int tid) {
#pragma unroll
    for (int i = 0; i < N2 / 64; i++) {
        int idx = i * 256 + tid;
        int r = idx >> 2;
        int c8 = (idx & 3) * 8;
        uint32_t off = (uint32_t)(r * (AST * 2) + c8 * 2);
        cpa16(wh + off, Whg + (size_t)r * Wstride + k0 + c8, true);
        if (WLO) cpa16(wl + off, Wlg + (size_t)r * Wstride + k0 + c8, true);
    }
}

// double-buffered GEMM core: KX halfs from global contiguous A, then KC from Cs smem.
// W rows live in an array of row-stride Wstride halfs (>= KX+KC).
template <int NT, bool WLO>
__device__ __forceinline__ void dbgemm(
    float d[2][NT][4],
    const __half* __restrict__ Ag, int m0, int KX,
    uint32_t cs_addr, int KC,
    const __half* __restrict__ Whg, const __half* __restrict__ Wlg, int Wstride,
    const uint32_t asb[2], const uint32_t whb[2], const uint32_t wlb[2],
    int tid, int lane, int Rm, int Cn) {
    const int Kfull = KX + KC;
    const int NTILES = Kfull / 32;
    // prologue
    if (KX > 0) loadA_cp(asb[0], Ag, m0, KX, 0, tid);
    loadW_cp<NT * 16, WLO>(whb[0], wlb[0], Whg, Wlg, Wstride, 0, tid);
    cpcommit();
    for (int t = 0; t < NTILES; t++) {
        if (t + 1 < NTILES) {
            int k1 = (t + 1) * 32;
            int nb = (t + 1) & 1;
            if (k1 < KX) loadA_cp(asb[nb], Ag, m0, KX, k1, tid);
            loadW_cp<NT * 16, WLO>(whb[nb], wlb[nb], Whg, Wlg, Wstride, k1, tid);
            cpcommit();
            cpwait1();
        } else {
            cpwait0();
        }
        __syncthreads();
        int k0 = t * 32;
        uint32_t Aaddr;
        int astr;
        if (k0 < KX) { Aaddr = asb[t & 1]; astr = AST; }
        else         { Aaddr = cs_addr + ((k0 - KX) << 1); astr = CST; }
        mma_tile_l<NT, WLO>(d, Aaddr, astr, whb[t & 1], wlb[t & 1], Rm, Cn, lane);
        __syncthreads();
    }
}

// ---------------- preprocessing ----------------
// zero degrees + (block 0) detect edge_index dtype
__global__ void zero_detect_k(const int* __restrict__ ei) {
    int i = blockIdx.x * 256 + threadIdx.x;
    if (i < N_NODES) g_degi[i] = 0;
    if (blockIdx.x == 0) {
        __shared__ int anynz;
        if (threadIdx.x == 0) anynz = 0;
        __syncthreads();
        if (ei[threadIdx.x * 2 + 1] != 0) anynz = 1;
        __syncthreads();
        if (threadIdx.x == 0) g_is64 = (anynz == 0) ? 1 : 0;
    }
}

// degree count straight from edge_index dst half
__global__ void deg_k(const void* __restrict__ ei) {
    int e = blockIdx.x * 256 + threadIdx.x;
    if (e >= N_EDGES) return;
    int d = g_is64 ? (int)((const long long*)ei)[N_EDGES + e]
                   : ((const int*)ei)[N_EDGES + e];
    atomicAdd(&g_degi[d], 1);
}

// weight matrices T1,W2,T2,W3,W4 pre-split (W1 handled after BN) + BN zero
__global__ void prepw_all_k(const float* __restrict__ T1,
                            const float* __restrict__ W2, const float* __restrict__ T2,
                            const float* __restrict__ W3, const float* __restrict__ W4,
                            __half* __restrict__ hi, __half* __restrict__ lo) {
    int idx = blockIdx.x * 256 + threadIdx.x;
    if (idx >= 77824) {
        int z = idx - 77824;
        if (z < 128)      g_bnsum[z] = 0.f;
        else if (z < 256) g_bnsq[z - 128] = 0.f;
        return;
    }
    if (idx < 8192) return;  // W1 region filled by bn_fold_k
    const float* src; int base, K, N;
    if (idx < 24576)      { src = T1; base = 8192;  K = 256; N = 64;  }
    else if (idx < 28672) { src = W2; base = 24576; K = 64;  N = 64;  }
    else if (idx < 45056) { src = T2; base = 28672; K = 256; N = 64;  }
    else if (idx < 69632) { src = W3; base = 45056; K = 192; N = 128; }
    else                  { src = W4; base = 69632; K = 128; N = 64;  }
    int r = idx - base;
    int k = r / N, n = r - k * N;
    float w = src[r];
    __half h = __float2half_rn(w);
    hi[base + n * K + k] = h;
    lo[base + n * K + k] = __float2half_rn(w - __half2float(h));
}

// block reduce of degrees + dis computation (fused)
__global__ void blkred_dis_k() {
    __shared__ int ws[8];
    int i = blockIdx.x * 256 + threadIdx.x;
    int v = (i < N_NODES) ? g_degi[i] : 0;
    if (i < N_NODES) g_dis[i] = (v > 0) ? rsqrtf((float)v) : 0.f;
    int s = v;
#pragma unroll
    for (int o = 16; o; o >>= 1) s += __shfl_down_sync(0xffffffffu, s, o);
    if ((threadIdx.x & 31) == 0) ws[threadIdx.x >> 5] = s;
    __syncthreads();
    if (threadIdx.x < 8) {
        int t = ws[threadIdx.x];
#pragma unroll
        for (int o = 4; o; o >>= 1) t += __shfl_down_sync(0xffu, t, o);
        if (threadIdx.x == 0) g_part[blockIdx.x] = t;
    }
}

__global__ void partscan_k(int nb) {
    __shared__ int ws[16];
    int t = threadIdx.x, lane = t & 31, w = t >> 5;
    int v = (t < nb) ? g_part[t] : 0;
    int x = v;
#pragma unroll
    for (int o = 1; o < 32; o <<= 1) {
        int y = __shfl_up_sync(0xffffffffu, x, o);
        if (lane >= o) x += y;
    }
    if (lane == 31) ws[w] = x;
    __syncthreads();
    if (w == 0 && lane < 16) {
        int s = ws[lane];
#pragma unroll
        for (int o = 1; o < 16; o <<= 1) {
            int y = __shfl_up_sync(0x0000ffffu, s, o);
            if (lane >= o) s += y;
        }
        ws[lane] = s;
    }
    __syncthreads();
    int pre = (w ? ws[w - 1] : 0) + x - v;
    if (t < nb) g_part[t] = pre;
    if (t == nb - 1) g_rowptr[N_NODES] = pre + v;
}

__global__ void blkscan_k() {
    __shared__ int ws[8];
    int t = threadIdx.x, lane = t & 31, w = t >> 5;
    int i = blockIdx.x * 256 + t;
    int v = (i < N_NODES) ? g_degi[i] : 0;
    int x = v;
#pragma unroll
    for (int o = 1; o < 32; o <<= 1) {
        int y = __shfl_up_sync(0xffffffffu, x, o);
        if (lane >= o) x += y;
    }
    if (lane == 31) ws[w] = x;
    __syncthreads();
    if (w == 0 && lane < 8) {
        int s = ws[lane];
#pragma unroll
        for (int o = 1; o < 8; o <<= 1) {
            int y = __shfl_up_sync(0x000000ffu, s, o);
            if (lane >= o) s += y;
        }
        ws[lane] = s;
    }
    __syncthreads();
    int ex = g_part[blockIdx.x] + (w ? ws[w - 1] : 0) + x - v;
    if (i < N_NODES) { g_rowptr[i] = ex; g_fill[i] = ex; }
}

// CSR fill straight from edge_index
__global__ void csrfill_k(const void* __restrict__ ei) {
    int e = blockIdx.x * 256 + threadIdx.x;
    if (e >= N_EDGES) return;
    int s, d;
    if (g_is64) {
        const long long* p = (const long long*)ei;
        s = (int)p[e];
        d = (int)p[N_EDGES + e];
    } else {
        const int* p = (const int*)ei;
        s = p[e];
        d = p[N_EDGES + e];
    }
    int pos = atomicAdd(&g_fill[d], 1);
    g_cw[pos] = make_int2(s, __float_as_int(g_dis[s] * g_dis[d]));
}

__global__ void bn_stats_k(const float* __restrict__ x) {
    int col = threadIdx.x & 127;
    int r = blockIdx.x * 2 + (threadIdx.x >> 7);
    float s = 0.f, q = 0.f;
    for (; r < N_NODES; r += gridDim.x * 2) {
        float v = x[(size_t)r * 128 + col];
        g_x16[(size_t)r * 128 + col] = __float2half_rn(v);
        s += v;
        q += v * v;
    }
    atomicAdd(&g_bnsum[col], s);
    atomicAdd(&g_bnsq[col], q);
}

// BN fold: blocks 0..31 split BN-scaled W1; block 32 folds bias b1' = b1 + t@W1
__global__ void bn_fold_k(const float* __restrict__ gamma, const float* __restrict__ beta,
                          const float* __restrict__ W1, const float* __restrict__ b1,
                          __half* __restrict__ hi, __half* __restrict__ lo) {
    int b = blockIdx.x, t = threadIdx.x;
    if (b < 32) {
        int idx = b * 256 + t;           // < 8192
        int k = idx >> 6, n = idx & 63;
        float mean = g_bnsum[k] * (1.0f / N_NODES);
        float var  = g_bnsq[k] * (1.0f / N_NODES) - mean * mean;
        float s = gamma[k] * rsqrtf(var + 1e-5f);
        float w = W1[idx] * s;
        __half h = __float2half_rn(w);
        hi[n * 128 + k] = h;
        lo[n * 128 + k] = __float2half_rn(w - __half2float(h));
    } else {
        __shared__ float ts[128];
        if (t < 128) {
            float mean = g_bnsum[t] * (1.0f / N_NODES);
            float var  = g_bnsq[t] * (1.0f / N_NODES) - mean * mean;
            float s = gamma[t] * rsqrtf(var + 1e-5f);
            ts[t] = beta[t] - mean * s;
        }
        __syncthreads();
        if (t < 64) {
            float acc = b1[t];
            for (int k = 0; k < 128; k++)
                acc += ts[k] * W1[k * 64 + t];
            g_b1f[t] = acc;
        }
    }
}

// CSR propagation on g_act segments: 4 nodes/warp, 8 lanes x uint4 per row.
__global__ void __launch_bounds__(256) prop_k(const __half* __restrict__ in,
                                              __half* __restrict__ out) {
    int w = blockIdx.x * 8 + (threadIdx.x >> 5);
    int lane = threadIdx.x & 31;
    int node = (w << 2) + (lane >> 3);
    int li = lane & 7;
    int beg = g_rowptr[node], end = g_rowptr[node + 1];
    float a0 = 0.f, a1 = 0.f, a2 = 0.f, a3 = 0.f;
    float a4 = 0.f, a5 = 0.f, a6 = 0.f, a7 = 0.f;
    int e = beg;
    while (__any_sync(0xffffffffu, e < end)) {
#pragma unroll
        for (int u = 0; u < 4; u++) {
            int ee = min(e + u, N_EDGES - 1);
            int2 c = __ldg(g_cw + ee);
            float wv = (e + u < end) ? __int_as_float(c.y) : 0.f;
            uint4 r = __ldg((const uint4*)(in + (size_t)c.x * 256) + li);
            float2 f0 = __half22float2(*(__half2*)&r.x);
            float2 f1 = __half22float2(*(__half2*)&r.y);
            float2 f2 = __half22float2(*(__half2*)&r.z);
            float2 f3 = __half22float2(*(__half2*)&r.w);
            a0 = fmaf(wv, f0.x, a0);
            a1 = fmaf(wv, f0.y, a1);
            a2 = fmaf(wv, f1.x, a2);
            a3 = fmaf(wv, f1.y, a3);
            a4 = fmaf(wv, f2.x, a4);
            a5 = fmaf(wv, f2.y, a5);
            a6 = fmaf(wv, f3.x, a6);
            a7 = fmaf(wv, f3.y, a7);
        }
        e += 4;
    }
    __half2 o0 = __floats2half2_rn(a0, a1);
    __half2 o1 = __floats2half2_rn(a2, a3);
    __half2 o2 = __floats2half2_rn(a4, a5);
    __half2 o3 = __floats2half2_rn(a6, a7);
    uint4 uo = make_uint4(*(uint32_t*)&o0, *(uint32_t*)&o1,
                          *(uint32_t*)&o2, *(uint32_t*)&o3);
    *((uint4*)(out + (size_t)node * 256) + li) = uo;
}

// ---------------- L1 GEMM: h = gelu(x16 @ W1' + b1') -> g_act seg0 ----------------
__global__ void __launch_bounds__(256) tgemm_l1_k(
    const __half* __restrict__ Ag,
    const __half* __restrict__ Whg, const __half* __restrict__ Wlg,
    __half* __restrict__ Cact) {
    __shared__ __half As[2][128][AST];
    __shared__ __half Wh[2][64][AST];
    __shared__ __half Wl[2][64][AST];

    int tid = threadIdx.x;
    int lane = tid & 31, wid = tid >> 5;
    int gid = lane >> 2, tg = lane & 3;
    int warp_m = wid & 3, warp_n = wid >> 2;
    int Rm = warp_m * 32;
    int Cn = warp_n * 32;
    int m0 = blockIdx.x * 128;

    uint32_t asb[2] = { smaddr(&As[0][0][0]), smaddr(&As[1][0][0]) };
    uint32_t whb[2] = { smaddr(&Wh[0][0][0]), smaddr(&Wh[1][0][0]) };
    uint32_t wlb[2] = { smaddr(&Wl[0][0][0]), smaddr(&Wl[1][0][0]) };

    float d[2][4][4];
#pragma unroll
    for (int mt = 0; mt < 2; mt++)
#pragma unroll
        for (int nt = 0; nt < 4; nt++)
#pragma unroll
            for (int q = 0; q < 4; q++) d[mt][nt][q] = 0.f;

    dbgemm<4, true>(d, Ag, m0, 128, 0u, 0, Whg, Wlg, 128, asb, whb, wlb,
                    tid, lane, Rm, Cn);

#pragma unroll
    for (int mt = 0; mt < 2; mt++) {
#pragma unroll
        for (int nt = 0; nt < 4; nt++) {
            int col = Cn + nt * 8 + tg * 2;
            float bx = g_b1f[col], by = g_b1f[col + 1];
            int r0 = m0 + Rm + mt * 16 + gid;
            int r1 = r0 + 8;
            float v0 = gelu_f(d[mt][nt][0] + bx), v1 = gelu_f(d[mt][nt][1] + by);
            float v2 = gelu_f(d[mt][nt][2] + bx), v3 = gelu_f(d[mt][nt][3] + by);
            if (r0 < N_NODES)
                *(__half2*)(Cact + (size_t)r0 * 256 + col) = __floats2half2_rn(v0, v1);
            if (r1 < N_NODES)
                *(__half2*)(Cact + (size_t)r1 * 256 + col) = __floats2half2_rn(v2, v3);
        }
    }
}

// ---------------- xpart GEMM: g_xp = x16 @ W3[0:128] (fp32, no bias/act) ----------
// W3 rows are [128][192]-strided; x-branch uses k offset 0.
__global__ void __launch_bounds__(256) xpart_k(
    const __half* __restrict__ Ag,
    const __half* __restrict__ Whg, const __half* __restrict__ Wlg,
    float* __restrict__ C) {
    extern __shared__ char sm[];
    uint32_t sbase = smaddr(sm);
    uint32_t asb[2] = { sbase, sbase + 10240 };
    uint32_t whb[2] = { sbase + 20480, sbase + 20480 + 2u * 128 * AST * 2 };
    uint32_t wlb[2] = { sbase + 20480 + 1u * 128 * AST * 2,
                        sbase + 20480 + 3u * 128 * AST * 2 };

    int tid = threadIdx.x;
    int lane = tid & 31, wid = tid >> 5;
    int gid = lane >> 2, tg = lane & 3;
    int warp_m = wid & 3, warp_n = wid >> 2;
    int Rm = warp_m * 32;
    int Cn = warp_n * 64;
    int m0 = blockIdx.x * 128;

    float d[2][8][4];
#pragma unroll
    for (int mt = 0; mt < 2; mt++)
#pragma unroll
        for (int nt = 0; nt < 8; nt++)
#pragma unroll
            for (int q = 0; q < 4; q++) d[mt][nt][q] = 0.f;

    dbgemm<8, true>(d, Ag, m0, 128, 0u, 0, Whg, Wlg, 192, asb, whb, wlb,
                    tid, lane, Rm, Cn);

#pragma unroll
    for (int mt = 0; mt < 2; mt++) {
#pragma unroll
        for (int nt = 0; nt < 8; nt++) {
            int col = Cn + nt * 8 + tg * 2;
            int r0 = m0 + Rm + mt * 16 + gid;
            int r1 = r0 + 8;
            if (r0 < N_NODES)
                *(float2*)(C + (size_t)r0 * 128 + col) =
                    make_float2(d[mt][nt][0], d[mt][nt][1]);
            if (r1 < N_NODES)
                *(float2*)(C + (size_t)r1 * 128 + col) =
                    make_float2(d[mt][nt][2], d[mt][nt][3]);
        }
    }
}

// ---------------- fused 2-stage chain GEMM ----------------
// stage1 (hi-only W): Cs = gelu(g_act[128 rows][256] @ Wa + ba), N=64 (smem)
// stage2: out = gelu(Cs @ Wb [+ partial] + bb), N2 -> fp16 global stride OS
// WBS = row stride of Wb arrays (192 for W3 h-branch, else 64)
template <int N2, int OS, bool ADDP, int WBS>
__global__ void __launch_bounds__(256) chain_k(
    const __half* __restrict__ act,
    const __half* __restrict__ Wahg,
    const float* __restrict__ ba,
    const __half* __restrict__ Wbhg, const __half* __restrict__ Wblg,
    const float* __restrict__ bb,
    const float* __restrict__ partial,
    __half* __restrict__ C16) {
    constexpr int NW = (N2 > 64) ? N2 : 64;
    extern __shared__ char sm[];
    // layout: As0 As1 | Cs | Wh0 Wl0 Wh1 Wl1
    uint32_t sbase = smaddr(sm);
    uint32_t asb[2] = { sbase, sbase + 10240 };
    uint32_t cs_a   = sbase + 20480;
    uint32_t whb[2] = { sbase + 38912, sbase + 38912 + 2u * NW * AST * 2 };
    uint32_t wlb[2] = { sbase + 38912 + 1u * NW * AST * 2,
                        sbase + 38912 + 3u * NW * AST * 2 };
    __half (*Cs)[CST] = (__half(*)[CST])(sm + 20480);

    int tid = threadIdx.x;
    int lane = tid & 31, wid = tid >> 5;
    int gid = lane >> 2, tg = lane & 3;
    int warp_m = wid & 3, warp_n = wid >> 2;
    int Rm = warp_m * 32;
    int m0 = blockIdx.x * 128;

    // -------- stage 1: K=256 from g_act, N=64, hi-only weights --------
    {
        int Cn = warp_n * 32;
        float d[2][4][4];
#pragma unroll
        for (int mt = 0; mt < 2; mt++)
#pragma unroll
            for (int nt = 0; nt < 4; nt++)
#pragma unroll
                for (int q = 0; q < 4; q++) d[mt][nt][q] = 0.f;

        dbgemm<4, false>(d, act, m0, 256, 0u, 0, Wahg, Wahg, 256, asb, whb, wlb,
                         tid, lane, Rm, Cn);

#pragma unroll
        for (int mt = 0; mt < 2; mt++) {
#pragma unroll
            for (int nt = 0; nt < 4; nt++) {
                int col = Cn + nt * 8 + tg * 2;
                float bx = ba[col], by = ba[col + 1];
                int r0 = Rm + mt * 16 + gid;
                *(__half2*)&Cs[r0][col] =
                    __floats2half2_rn(gelu_f(d[mt][nt][0] + bx), gelu_f(d[mt][nt][1] + by));
                *(__half2*)&Cs[r0 + 8][col] =
                    __floats2half2_rn(gelu_f(d[mt][nt][2] + bx), gelu_f(d[mt][nt][3] + by));
            }
        }
    }
    __syncthreads();

    // -------- stage 2: K = 64 (Cs), N = N2 --------
    {
        constexpr int NT = N2 / 16;
        int Cn = warp_n * (N2 / 2);
        float d[2][NT][4];
#pragma unroll
        for (int mt = 0; mt < 2; mt++)
#pragma unroll
            for (int nt = 0; nt < NT; nt++)
#pragma unroll
                for (int q = 0; q < 4; q++) d[mt][nt][q] = 0.f;

        dbgemm<NT, true>(d, nullptr, m0, 0, cs_a, 64, Wbhg, Wblg, WBS,
                         asb, whb, wlb, tid, lane, Rm, Cn);

#pragma unroll
        for (int mt = 0; mt < 2; mt++) {
#pragma unroll
            for (int nt = 0; nt < NT; nt++) {
                int col = Cn + nt * 8 + tg * 2;
                float bx = bb[col], by = bb[col + 1];
                int r0 = m0 + Rm + mt * 16 + gid;
                int r1 = r0 + 8;
                float v0 = d[mt][nt][0] + bx, v1 = d[mt][nt][1] + by;
                float v2 = d[mt][nt][2] + bx, v3 = d[mt][nt][3] + by;
                if (ADDP) {
                    if (r0 < N_NODES) {
                        float2 p = *(const float2*)(partial + (size_t)r0 * N2 + col);
                        v0 += p.x; v1 += p.y;
                    }
                    if (r1 < N_NODES) {
                        float2 p = *(const float2*)(partial + (size_t)r1 * N2 + col);
                        v2 += p.x; v3 += p.y;
                    }
                }
                v0 = gelu_f(v0); v1 = gelu_f(v1); v2 = gelu_f(v2); v3 = gelu_f(v3);
                if (r0 < N_NODES)
                    *(__half2*)(C16 + (size_t)r0 * OS + col) = __floats2half2_rn(v0, v1);
                if (r1 < N_NODES)
                    *(__half2*)(C16 + (size_t)r1 * OS + col) = __floats2half2_rn(v2, v3);
            }
        }
    }
}

// ---------------- L4 GEMM: out = a16 @ W4 + b4 (fp32 out) ----------------
__global__ void __launch_bounds__(256) tgemm16_k(
    const __half* __restrict__ Ag,
    const __half* __restrict__ Whg, const __half* __restrict__ Wlg,
    const float* __restrict__ bias, float* __restrict__ C) {
    __shared__ __half As[2][128][AST];
    __shared__ __half Wh[2][64][AST];
    __shared__ __half Wl[2][64][AST];

    int tid = threadIdx.x;
    int lane = tid & 31, wid = tid >> 5;
    int gid = lane >> 2, tg = lane & 3;
    int warp_m = wid & 3, warp_n = wid >> 2;
    int Rm = warp_m * 32;
    int Cn = warp_n * 32;
    int m0 = blockIdx.x * 128;

    uint32_t asb[2] = { smaddr(&As[0][0][0]), smaddr(&As[1][0][0]) };
    uint32_t whb[2] = { smaddr(&Wh[0][0][0]), smaddr(&Wh[1][0][0]) };
    uint32_t wlb[2] = { smaddr(&Wl[0][0][0]), smaddr(&Wl[1][0][0]) };

    float d[2][4][4];
#pragma unroll
    for (int mt = 0; mt < 2; mt++)
#pragma unroll
        for (int nt = 0; nt < 4; nt++)
#pragma unroll
            for (int q = 0; q < 4; q++) d[mt][nt][q] = 0.f;

    dbgemm<4, true>(d, Ag, m0, 128, 0u, 0, Whg, Wlg, 128, asb, whb, wlb,
                    tid, lane, Rm, Cn);

#pragma unroll
    for (int mt = 0; mt < 2; mt++) {
#pragma unroll
        for (int nt = 0; nt < 4; nt++) {
            int col = Cn + nt * 8 + tg * 2;
            float bx = bias[col], by = bias[col + 1];
            int r0 = m0 + Rm + mt * 16 + gid;
            int r1 = r0 + 8;
            if (r0 < N_NODES)
                *(float2*)(C + (size_t)r0 * 64 + col) =
                    make_float2(d[mt][nt][0] + bx, d[mt][nt][1] + by);
            if (r1 < N_NODES)
                *(float2*)(C + (size_t)r1 * 64 + col) =
                    make_float2(d[mt][nt][2] + bx, d[mt][nt][3] + by);
        }
    }
}

// ---------------- host launcher ----------------
extern "C" void kernel_launch(void* const* d_in, const int* in_sizes, int n_in,
                              void* d_out, int out_size) {
    const float* x     = (const float*)d_in[0];
    const void*  ei    = d_in[1];
    const float* gamma = (const float*)d_in[2];
    const float* beta  = (const float*)d_in[3];
    const float* W1 = (const float*)d_in[4];  const float* b1  = (const float*)d_in[5];
    const float* T1 = (const float*)d_in[6];  const float* t1b = (const float*)d_in[7];
    const float* W2 = (const float*)d_in[8];  const float* b2  = (const float*)d_in[9];
    const float* T2 = (const float*)d_in[10]; const float* t2b = (const float*)d_in[11];
    const float* W3 = (const float*)d_in[12]; const float* b3  = (const float*)d_in[13];
    const float* W4 = (const float*)d_in[14]; const float* b4  = (const float*)d_in[15];
    float* out = (float*)d_out;

    __half *x16, *a16, *act, *wthi, *wtlo;
    float *xp;
    cudaGetSymbolAddress((void**)&x16,  g_x16);
    cudaGetSymbolAddress((void**)&a16,  g_a16);
    cudaGetSymbolAddress((void**)&act,  g_act);
    cudaGetSymbolAddress((void**)&wthi, g_wthi);
    cudaGetSymbolAddress((void**)&wtlo, g_wtlo);
    cudaGetSymbolAddress((void**)&xp,   g_xp);

    const int OT1 = 8192, OW2 = 24576, OT2 = 28672, OW3 = 45056, OW4 = 69632;

    const int EB = (N_EDGES + 255) / 256;
    const int NB = (N_NODES + 255) / 256;   // 391
    const int GB = (N_NODES + 127) / 128;   // 782
    const int PB = N_NODES / 32;            // 3125 (4 nodes/warp, 8 warps/block)

    const int SM_C1 = 38912 + 64  * AST * 2 * 4;  // 59392
    const int SM_C2 = 38912 + 128 * AST * 2 * 4;  // 79872
    const int SM_XP = 20480 + 128 * AST * 2 * 4;  // 61440
    cudaFuncSetAttribute((const void*)chain_k<64, 256, false, 64>,
                         cudaFuncAttributeMaxDynamicSharedMemorySize, SM_C1);
    cudaFuncSetAttribute((const void*)chain_k<128, 128, true, 192>,
                         cudaFuncAttributeMaxDynamicSharedMemorySize, SM_C2);
    cudaFuncSetAttribute((const void*)xpart_k,
                         cudaFuncAttributeMaxDynamicSharedMemorySize, SM_XP);

    // fork: weights/BN/L1/xpart on s1, graph preprocessing on stream 0
    cudaStream_t s1;
    cudaStreamCreateWithFlags(&s1, cudaStreamNonBlocking);
    cudaEvent_t e0, e1, e2;
    cudaEventCreateWithFlags(&e0, cudaEventDisableTiming);
    cudaEventCreateWithFlags(&e1, cudaEventDisableTiming);
    cudaEventCreateWithFlags(&e2, cudaEventDisableTiming);
    cudaEventRecord(e0, 0);
    cudaStreamWaitEvent(s1, e0, 0);

    // ---- stream s1 ----
    prepw_all_k<<<305, 256, 0, s1>>>(T1, W2, T2, W3, W4, wthi, wtlo);
    bn_stats_k<<<512, 256, 0, s1>>>(x);
    bn_fold_k<<<33, 256, 0, s1>>>(gamma, beta, W1, b1, wthi, wtlo);
    tgemm_l1_k<<<GB, 256, 0, s1>>>(x16, wthi, wtlo, act);
    cudaEventRecord(e1, s1);
    // xpart runs concurrently with stream-0 TAG1 work (only needed at chain2)
    xpart_k<<<GB, 256, SM_XP, s1>>>(x16, wthi + OW3, wtlo + OW3, xp);
    cudaEventRecord(e2, s1);

    // ---- stream 0: graph preprocessing ----
    zero_detect_k<<<NB, 256>>>((const int*)ei);
    deg_k<<<EB, 256>>>(ei);
    blkred_dis_k<<<NB, 256>>>();
    partscan_k<<<1, 512>>>(NB);
    blkscan_k<<<NB, 256>>>();
    csrfill_k<<<EB, 256>>>(ei);

    cudaStreamWaitEvent(0, e1, 0);   // join: props need CSR + h

    // ---- TAGConv1: props fill segs 1..3, then chain (TAG1 + L2) -> h in seg0 ----
    prop_k<<<PB, 256>>>(act,       act + 64);
    prop_k<<<PB, 256>>>(act + 64,  act + 128);
    prop_k<<<PB, 256>>>(act + 128, act + 192);
    chain_k<64, 256, false, 64><<<GB, 256, SM_C1>>>(
        act, wthi + OT1, t1b, wthi + OW2, wtlo + OW2, b2, nullptr, act);

    // ---- TAGConv2: props, then chain (TAG2 + L3 with precomputed x-partial) ----
    prop_k<<<PB, 256>>>(act,       act + 64);
    prop_k<<<PB, 256>>>(act + 64,  act + 128);
    prop_k<<<PB, 256>>>(act + 128, act + 192);
    cudaStreamWaitEvent(0, e2, 0);   // xpart must be done
    chain_k<128, 128, true, 192><<<GB, 256, SM_C2>>>(
        act, wthi + OT2, t2b, wthi + OW3 + 128, wtlo + OW3 + 128, b3, xp, a16);

    // ---- layer 4 ----
    tgemm16_k<<<GB, 256>>>(a16, wthi + OW4, wtlo + OW4, b4, out);
}

// round 13
// speedup vs baseline: 1.0849x; 1.0849x over previous
#include <cuda_runtime.h>
#include <cuda_fp16.h>
#include <math.h>
#include <stdint.h>

#define N_NODES 100000
#define N_EDGES 1000000
#define AST 40   // A/W tile half stride (ldmatrix conflict-free, 16B-aligned rows)
#define CST 72   // Cs half stride

// ---------------- device scratch ----------------
__device__ int   g_is64;
__device__ __align__(16) int   g_degi[N_NODES];
__device__ __align__(16) float g_dis[N_NODES];
__device__ __align__(16) int   g_rowptr[N_NODES + 1];
__device__ __align__(16) int   g_fill[N_NODES];
__device__ __align__(16) int2  g_cw[N_EDGES];
__device__ __align__(16) int   g_part[512];
__device__ __align__(16) float g_bnsum[128];
__device__ __align__(16) float g_bnsq[128];
__device__ __align__(16) float g_b1f[64];     // folded bias: b1 + t @ W1
__device__ __align__(16) __half g_x16[N_NODES * 128];
__device__ __align__(16) __half g_a16[N_NODES * 128];
// unified activation buffer: cols [0,64)=h [64,128)=Ah [128,192)=A2h [192,256)=A3h
__device__ __align__(16) __half g_act[N_NODES * 256];
// pre-split transposed weights: hi/lo fp16, [N][K] k-major
// W1(scaled)=0(8192) T1=8192 W2=24576 T2=28672 W3=45056 W4=69632
__device__ __align__(16) __half g_wthi[77824];
__device__ __align__(16) __half g_wtlo[77824];

// ---------------- helpers ----------------
__device__ __forceinline__ float gelu_f(float v) {
    return 0.5f * v * (1.0f + erff(v * 0.70710678118654752440f));
}

__device__ __forceinline__ void mmaf16(float d[4], const uint32_t a[4],
                                       uint32_t b0, uint32_t b1) {
    asm volatile(
        "mma.sync.aligned.m16n8k16.row.col.f32.f16.f16.f32 "
        "{%0,%1,%2,%3}, {%4,%5,%6,%7}, {%8,%9}, {%0,%1,%2,%3};"
        : "+f"(d[0]), "+f"(d[1]), "+f"(d[2]), "+f"(d[3])
        : "r"(a[0]), "r"(a[1]), "r"(a[2]), "r"(a[3]), "r"(b0), "r"(b1));
}

__device__ __forceinline__ void ldsm_x4(uint32_t r[4], uint32_t a) {
    asm volatile("ldmatrix.sync.aligned.m8n8.x4.shared.b16 {%0,%1,%2,%3}, [%4];"
        : "=r"(r[0]), "=r"(r[1]), "=r"(r[2]), "=r"(r[3]) : "r"(a));
}

__device__ __forceinline__ uint32_t smaddr(const void* p) {
    return (uint32_t)__cvta_generic_to_shared(p);
}

__device__ __forceinline__ void cpa16(uint32_t dst, const void* src, bool p) {
    int sz = p ? 16 : 0;
    asm volatile("cp.async.cg.shared.global [%0], [%1], 16, %2;"
        :: "r"(dst), "l"(src), "r"(sz));
}
__device__ __forceinline__ void cpcommit() { asm volatile("cp.async.commit_group;"); }
__device__ __forceinline__ void cpwait1()  { asm volatile("cp.async.wait_group 1;"); }
__device__ __forceinline__ void cpwait0()  { asm volatile("cp.async.wait_group 0;"); }

// one 32-K step of mma with ldmatrix fragments; WLO = use lo-half of W split
template <int NT, bool WLO>
__device__ __forceinline__ void mma_tile_l(
    float d[2][NT][4], uint32_t Ab_addr, int astr,
    uint32_t Wh_addr, uint32_t Wl_addr,
    int Rm, int Cn, int lane) {
#pragma unroll
    for (int ks = 0; ks < 2; ks++) {
        int kk = ks * 16;
        uint32_t a[2][4];
#pragma unroll
        for (int mt = 0; mt < 2; mt++) {
            int row = Rm + 16 * mt + (lane & 15);
            int kof = kk + 8 * (lane >> 4);
            ldsm_x4(a[mt], Ab_addr + ((row * astr + kof) << 1));
        }
        uint32_t bh[NT / 2][4], bl[NT / 2][4];
#pragma unroll
        for (int q = 0; q < NT / 2; q++) {
            int row = Cn + q * 16 + (lane & 7) + ((lane >> 4) << 3);
            int kof = kk + 8 * ((lane >> 3) & 1);
            uint32_t off = (uint32_t)((row * AST + kof) << 1);
            ldsm_x4(bh[q], Wh_addr + off);
            if (WLO) ldsm_x4(bl[q], Wl_addr + off);
        }
#pragma unroll
        for (int q = 0; q < NT / 2; q++) {
#pragma unroll
            for (int h = 0; h < 2; h++) {
                int nt = q * 2 + h;
#pragma unroll
                for (int mt = 0; mt < 2; mt++) {
                    mmaf16(d[mt][nt], a[mt], bh[q][2 * h], bh[q][2 * h + 1]);
                    if (WLO) mmaf16(d[mt][nt], a[mt], bl[q][2 * h], bl[q][2 * h + 1]);
                }
            }
        }
    }
}

// A tile cp.async: 128 rows x 32 halfs from contiguous fp16 [.][KX]
__device__ __forceinline__ void loadA_cp(uint32_t asbuf, const __half* Ag,
                                         int m0, int KX, int k0, int tid) {
#pragma unroll
    for (int i = 0; i < 2; i++) {
        int idx = i * 256 + tid;
        int r = idx >> 2;
        int c8 = (idx & 3) * 8;
        int gr = m0 + r;
        bool p = gr < N_NODES;
        int rr = p ? gr : (N_NODES - 1);
        cpa16(asbuf + r * (AST * 2) + c8 * 2,
              Ag + (size_t)rr * KX + k0 + c8, p);
    }
}

// W tile cp.async: N2 rows x 32 halfs from [N2][Wstride] (hi, and lo if WLO)
template <int N2, bool WLO>
__device__ __forceinline__ void loadW_cp(uint32_t wh, uint32_t wl,
                                         const __half* Whg, const __half* Wlg,
                                         int Wstride, int k0, int tid) {
#pragma unroll
    for (int i = 0; i < N2 / 64; i++) {
        int idx = i * 256 + tid;
        int r = idx >> 2;
        int c8 = (idx & 3) * 8;
        uint32_t off = (uint32_t)(r * (AST * 2) + c8 * 2);
        cpa16(wh + off, Whg + (size_t)r * Wstride + k0 + c8, true);
        if (WLO) cpa16(wl + off, Wlg + (size_t)r * Wstride + k0 + c8, true);
    }
}

// double-buffered GEMM core: KX halfs from global contiguous A, then KC from Cs smem.
// W rows live in an array of row-stride Wstride halfs (>= KX+KC).
template <int NT, bool WLO>
__device__ __forceinline__ void dbgemm(
    float d[2][NT][4],
    const __half* __restrict__ Ag, int m0, int KX,
    uint32_t cs_addr, int KC,
    const __half* __restrict__ Whg, const __half* __restrict__ Wlg, int Wstride,
    const uint32_t asb[2], const uint32_t whb[2], const uint32_t wlb[2],
    int tid, int lane, int Rm, int Cn) {
    const int Kfull = KX + KC;
    const int NTILES = Kfull / 32;
    // prologue
    if (KX > 0) loadA_cp(asb[0], Ag, m0, KX, 0, tid);
    loadW_cp<NT * 16, WLO>(whb[0], wlb[0], Whg, Wlg, Wstride, 0, tid);
    cpcommit();
    for (int t = 0; t < NTILES; t++) {
        if (t + 1 < NTILES) {
            int k1 = (t + 1) * 32;
            int nb = (t + 1) & 1;
            if (k1 < KX) loadA_cp(asb[nb], Ag, m0, KX, k1, tid);
            loadW_cp<NT * 16, WLO>(whb[nb], wlb[nb], Whg, Wlg, Wstride, k1, tid);
            cpcommit();
            cpwait1();
        } else {
            cpwait0();
        }
        __syncthreads();
        int k0 = t * 32;
        uint32_t Aaddr;
        int astr;
        if (k0 < KX) { Aaddr = asb[t & 1]; astr = AST; }
        else         { Aaddr = cs_addr + ((k0 - KX) << 1); astr = CST; }
        mma_tile_l<NT, WLO>(d, Aaddr, astr, whb[t & 1], wlb[t & 1], Rm, Cn, lane);
        __syncthreads();
    }
}

// ---------------- preprocessing ----------------
// zero degrees + (block 0) detect edge_index dtype
__global__ void zero_detect_k(const int* __restrict__ ei) {
    int i = blockIdx.x * 256 + threadIdx.x;
    if (i < N_NODES) g_degi[i] = 0;
    if (blockIdx.x == 0) {
        __shared__ int anynz;
        if (threadIdx.x == 0) anynz = 0;
        __syncthreads();
        if (ei[threadIdx.x * 2 + 1] != 0) anynz = 1;
        __syncthreads();
        if (threadIdx.x == 0) g_is64 = (anynz == 0) ? 1 : 0;
    }
}

// degree count straight from edge_index dst half
__global__ void deg_k(const void* __restrict__ ei) {
    int e = blockIdx.x * 256 + threadIdx.x;
    if (e >= N_EDGES) return;
    int d = g_is64 ? (int)((const long long*)ei)[N_EDGES + e]
                   : ((const int*)ei)[N_EDGES + e];
    atomicAdd(&g_degi[d], 1);
}

// weight matrices T1,W2,T2,W3,W4 pre-split (W1 handled after BN) + BN zero
__global__ void prepw_all_k(const float* __restrict__ T1,
                            const float* __restrict__ W2, const float* __restrict__ T2,
                            const float* __restrict__ W3, const float* __restrict__ W4,
                            __half* __restrict__ hi, __half* __restrict__ lo) {
    int idx = blockIdx.x * 256 + threadIdx.x;
    if (idx >= 77824) {
        int z = idx - 77824;
        if (z < 128)      g_bnsum[z] = 0.f;
        else if (z < 256) g_bnsq[z - 128] = 0.f;
        return;
    }
    if (idx < 8192) return;  // W1 region filled by bn_fold_k
    const float* src; int base, K, N;
    if (idx < 24576)      { src = T1; base = 8192;  K = 256; N = 64;  }
    else if (idx < 28672) { src = W2; base = 24576; K = 64;  N = 64;  }
    else if (idx < 45056) { src = T2; base = 28672; K = 256; N = 64;  }
    else if (idx < 69632) { src = W3; base = 45056; K = 192; N = 128; }
    else                  { src = W4; base = 69632; K = 128; N = 64;  }
    int r = idx - base;
    int k = r / N, n = r - k * N;
    float w = src[r];
    __half h = __float2half_rn(w);
    hi[base + n * K + k] = h;
    lo[base + n * K + k] = __float2half_rn(w - __half2float(h));
}

// block reduce of degrees + dis computation (fused)
__global__ void blkred_dis_k() {
    __shared__ int ws[8];
    int i = blockIdx.x * 256 + threadIdx.x;
    int v = (i < N_NODES) ? g_degi[i] : 0;
    if (i < N_NODES) g_dis[i] = (v > 0) ? rsqrtf((float)v) : 0.f;
    int s = v;
#pragma unroll
    for (int o = 16; o; o >>= 1) s += __shfl_down_sync(0xffffffffu, s, o);
    if ((threadIdx.x & 31) == 0) ws[threadIdx.x >> 5] = s;
    __syncthreads();
    if (threadIdx.x < 8) {
        int t = ws[threadIdx.x];
#pragma unroll
        for (int o = 4; o; o >>= 1) t += __shfl_down_sync(0xffu, t, o);
        if (threadIdx.x == 0) g_part[blockIdx.x] = t;
    }
}

__global__ void partscan_k(int nb) {
    __shared__ int ws[16];
    int t = threadIdx.x, lane = t & 31, w = t >> 5;
    int v = (t < nb) ? g_part[t] : 0;
    int x = v;
#pragma unroll
    for (int o = 1; o < 32; o <<= 1) {
        int y = __shfl_up_sync(0xffffffffu, x, o);
        if (lane >= o) x += y;
    }
    if (lane == 31) ws[w] = x;
    __syncthreads();
    if (w == 0 && lane < 16) {
        int s = ws[lane];
#pragma unroll
        for (int o = 1; o < 16; o <<= 1) {
            int y = __shfl_up_sync(0x0000ffffu, s, o);
            if (lane >= o) s += y;
        }
        ws[lane] = s;
    }
    __syncthreads();
    int pre = (w ? ws[w - 1] : 0) + x - v;
    if (t < nb) g_part[t] = pre;
    if (t == nb - 1) g_rowptr[N_NODES] = pre + v;
}

__global__ void blkscan_k() {
    __shared__ int ws[8];
    int t = threadIdx.x, lane = t & 31, w = t >> 5;
    int i = blockIdx.x * 256 + t;
    int v = (i < N_NODES) ? g_degi[i] : 0;
    int x = v;
#pragma unroll
    for (int o = 1; o < 32; o <<= 1) {
        int y = __shfl_up_sync(0xffffffffu, x, o);
        if (lane >= o) x += y;
    }
    if (lane == 31) ws[w] = x;
    __syncthreads();
    if (w == 0 && lane < 8) {
        int s = ws[lane];
#pragma unroll
        for (int o = 1; o < 8; o <<= 1) {
            int y = __shfl_up_sync(0x000000ffu, s, o);
            if (lane >= o) s += y;
        }
        ws[lane] = s;
    }
    __syncthreads();
    int ex = g_part[blockIdx.x] + (w ? ws[w - 1] : 0) + x - v;
    if (i < N_NODES) { g_rowptr[i] = ex; g_fill[i] = ex; }
}

// CSR fill straight from edge_index
__global__ void csrfill_k(const void* __restrict__ ei) {
    int e = blockIdx.x * 256 + threadIdx.x;
    if (e >= N_EDGES) return;
    int s, d;
    if (g_is64) {
        const long long* p = (const long long*)ei;
        s = (int)p[e];
        d = (int)p[N_EDGES + e];
    } else {
        const int* p = (const int*)ei;
        s = p[e];
        d = p[N_EDGES + e];
    }
    int pos = atomicAdd(&g_fill[d], 1);
    g_cw[pos] = make_int2(s, __float_as_int(g_dis[s] * g_dis[d]));
}

__global__ void bn_stats_k(const float* __restrict__ x) {
    int col = threadIdx.x & 127;
    int r = blockIdx.x * 2 + (threadIdx.x >> 7);
    float s = 0.f, q = 0.f;
    for (; r < N_NODES; r += gridDim.x * 2) {
        float v = x[(size_t)r * 128 + col];
        g_x16[(size_t)r * 128 + col] = __float2half_rn(v);
        s += v;
        q += v * v;
    }
    atomicAdd(&g_bnsum[col], s);
    atomicAdd(&g_bnsq[col], q);
}

// BN fold: blocks 0..31 split BN-scaled W1; block 32 folds bias b1' = b1 + t@W1
__global__ void bn_fold_k(const float* __restrict__ gamma, const float* __restrict__ beta,
                          const float* __restrict__ W1, const float* __restrict__ b1,
                          __half* __restrict__ hi, __half* __restrict__ lo) {
    int b = blockIdx.x, t = threadIdx.x;
    if (b < 32) {
        int idx = b * 256 + t;           // < 8192
        int k = idx >> 6, n = idx & 63;
        float mean = g_bnsum[k] * (1.0f / N_NODES);
        float var  = g_bnsq[k] * (1.0f / N_NODES) - mean * mean;
        float s = gamma[k] * rsqrtf(var + 1e-5f);
        float w = W1[idx] * s;
        __half h = __float2half_rn(w);
        hi[n * 128 + k] = h;
        lo[n * 128 + k] = __float2half_rn(w - __half2float(h));
    } else {
        __shared__ float ts[128];
        if (t < 128) {
            float mean = g_bnsum[t] * (1.0f / N_NODES);
            float var  = g_bnsq[t] * (1.0f / N_NODES) - mean * mean;
            float s = gamma[t] * rsqrtf(var + 1e-5f);
            ts[t] = beta[t] - mean * s;
        }
        __syncthreads();
        if (t < 64) {
            float acc = b1[t];
            for (int k = 0; k < 128; k++)
                acc += ts[k] * W1[k * 64 + t];
            g_b1f[t] = acc;
        }
    }
}

// CSR propagation on g_act segments: 4 nodes/warp, 8 lanes x uint4 per row.
__global__ void __launch_bounds__(256) prop_k(const __half* __restrict__ in,
                                              __half* __restrict__ out) {
    int w = blockIdx.x * 8 + (threadIdx.x >> 5);
    int lane = threadIdx.x & 31;
    int node = (w << 2) + (lane >> 3);
    int li = lane & 7;
    int beg = g_rowptr[node], end = g_rowptr[node + 1];
    float a0 = 0.f, a1 = 0.f, a2 = 0.f, a3 = 0.f;
    float a4 = 0.f, a5 = 0.f, a6 = 0.f, a7 = 0.f;
    int e = beg;
    while (__any_sync(0xffffffffu, e < end)) {
#pragma unroll
        for (int u = 0; u < 4; u++) {
            int ee = min(e + u, N_EDGES - 1);
            int2 c = __ldg(g_cw + ee);
            float wv = (e + u < end) ? __int_as_float(c.y) : 0.f;
            uint4 r = __ldg((const uint4*)(in + (size_t)c.x * 256) + li);
            float2 f0 = __half22float2(*(__half2*)&r.x);
            float2 f1 = __half22float2(*(__half2*)&r.y);
            float2 f2 = __half22float2(*(__half2*)&r.z);
            float2 f3 = __half22float2(*(__half2*)&r.w);
            a0 = fmaf(wv, f0.x, a0);
            a1 = fmaf(wv, f0.y, a1);
            a2 = fmaf(wv, f1.x, a2);
            a3 = fmaf(wv, f1.y, a3);
            a4 = fmaf(wv, f2.x, a4);
            a5 = fmaf(wv, f2.y, a5);
            a6 = fmaf(wv, f3.x, a6);
            a7 = fmaf(wv, f3.y, a7);
        }
        e += 4;
    }
    __half2 o0 = __floats2half2_rn(a0, a1);
    __half2 o1 = __floats2half2_rn(a2, a3);
    __half2 o2 = __floats2half2_rn(a4, a5);
    __half2 o3 = __floats2half2_rn(a6, a7);
    uint4 uo = make_uint4(*(uint32_t*)&o0, *(uint32_t*)&o1,
                          *(uint32_t*)&o2, *(uint32_t*)&o3);
    *((uint4*)(out + (size_t)node * 256) + li) = uo;
}

// ---------------- L1 GEMM: h = gelu(x16 @ W1' + b1') -> g_act seg0 ----------------
__global__ void __launch_bounds__(256) tgemm_l1_k(
    const __half* __restrict__ Ag,
    const __half* __restrict__ Whg, const __half* __restrict__ Wlg,
    __half* __restrict__ Cact) {
    __shared__ __half As[2][128][AST];
    __shared__ __half Wh[2][64][AST];
    __shared__ __half Wl[2][64][AST];

    int tid = threadIdx.x;
    int lane = tid & 31, wid = tid >> 5;
    int gid = lane >> 2, tg = lane & 3;
    int warp_m = wid & 3, warp_n = wid >> 2;
    int Rm = warp_m * 32;
    int Cn = warp_n * 32;
    int m0 = blockIdx.x * 128;

    uint32_t asb[2] = { smaddr(&As[0][0][0]), smaddr(&As[1][0][0]) };
    uint32_t whb[2] = { smaddr(&Wh[0][0][0]), smaddr(&Wh[1][0][0]) };
    uint32_t wlb[2] = { smaddr(&Wl[0][0][0]), smaddr(&Wl[1][0][0]) };

    float d[2][4][4];
#pragma unroll
    for (int mt = 0; mt < 2; mt++)
#pragma unroll
        for (int nt = 0; nt < 4; nt++)
#pragma unroll
            for (int q = 0; q < 4; q++) d[mt][nt][q] = 0.f;

    dbgemm<4, true>(d, Ag, m0, 128, 0u, 0, Whg, Wlg, 128, asb, whb, wlb,
                    tid, lane, Rm, Cn);

#pragma unroll
    for (int mt = 0; mt < 2; mt++) {
#pragma unroll
        for (int nt = 0; nt < 4; nt++) {
            int col = Cn + nt * 8 + tg * 2;
            float bx = g_b1f[col], by = g_b1f[col + 1];
            int r0 = m0 + Rm + mt * 16 + gid;
            int r1 = r0 + 8;
            float v0 = gelu_f(d[mt][nt][0] + bx), v1 = gelu_f(d[mt][nt][1] + by);
            float v2 = gelu_f(d[mt][nt][2] + bx), v3 = gelu_f(d[mt][nt][3] + by);
            if (r0 < N_NODES)
                *(__half2*)(Cact + (size_t)r0 * 256 + col) = __floats2half2_rn(v0, v1);
            if (r1 < N_NODES)
                *(__half2*)(Cact + (size_t)r1 * 256 + col) = __floats2half2_rn(v2, v3);
        }
    }
}

// ---------------- fused 2-stage chain GEMM ----------------
// stage1 (hi-only W): Cs = gelu(g_act[128 rows][256] @ Wa + ba), N=64 (smem)
// stage2: out = gelu(concat(xg[XW], Cs) @ Wb + bb), N2 -> fp16 global stride OS
// WB row stride = XW + 64; WBLO selects hi-only vs hi/lo for Wb.
template <int XW, int N2, int OS, bool WBLO>
__global__ void __launch_bounds__(256) chain_k(
    const __half* __restrict__ act,
    const __half* __restrict__ Wahg,
    const float* __restrict__ ba,
    const __half* __restrict__ xg,
    const __half* __restrict__ Wbhg, const __half* __restrict__ Wblg,
    const float* __restrict__ bb,
    __half* __restrict__ C16) {
    constexpr int NW = (N2 > 64) ? N2 : 64;
    extern __shared__ char sm[];
    // layout: As0 As1 | Cs | Wh0 Wl0 Wh1 Wl1
    uint32_t sbase = smaddr(sm);
    uint32_t asb[2] = { sbase, sbase + 10240 };
    uint32_t cs_a   = sbase + 20480;
    uint32_t whb[2] = { sbase + 38912, sbase + 38912 + 2u * NW * AST * 2 };
    uint32_t wlb[2] = { sbase + 38912 + 1u * NW * AST * 2,
                        sbase + 38912 + 3u * NW * AST * 2 };
    __half (*Cs)[CST] = (__half(*)[CST])(sm + 20480);

    int tid = threadIdx.x;
    int lane = tid & 31, wid = tid >> 5;
    int gid = lane >> 2, tg = lane & 3;
    int warp_m = wid & 3, warp_n = wid >> 2;
    int Rm = warp_m * 32;
    int m0 = blockIdx.x * 128;

    // -------- stage 1: K=256 from g_act, N=64, hi-only weights --------
    {
        int Cn = warp_n * 32;
        float d[2][4][4];
#pragma unroll
        for (int mt = 0; mt < 2; mt++)
#pragma unroll
            for (int nt = 0; nt < 4; nt++)
#pragma unroll
                for (int q = 0; q < 4; q++) d[mt][nt][q] = 0.f;

        dbgemm<4, false>(d, act, m0, 256, 0u, 0, Wahg, Wahg, 256, asb, whb, wlb,
                         tid, lane, Rm, Cn);

#pragma unroll
        for (int mt = 0; mt < 2; mt++) {
#pragma unroll
            for (int nt = 0; nt < 4; nt++) {
                int col = Cn + nt * 8 + tg * 2;
                float bx = ba[col], by = ba[col + 1];
                int r0 = Rm + mt * 16 + gid;
                *(__half2*)&Cs[r0][col] =
                    __floats2half2_rn(gelu_f(d[mt][nt][0] + bx), gelu_f(d[mt][nt][1] + by));
                *(__half2*)&Cs[r0 + 8][col] =
                    __floats2half2_rn(gelu_f(d[mt][nt][2] + bx), gelu_f(d[mt][nt][3] + by));
            }
        }
    }
    __syncthreads();

    // -------- stage 2: K = XW (global x16) + 64 (Cs), N = N2 --------
    {
        constexpr int NT = N2 / 16;
        int Cn = warp_n * (N2 / 2);
        float d[2][NT][4];
#pragma unroll
        for (int mt = 0; mt < 2; mt++)
#pragma unroll
            for (int nt = 0; nt < NT; nt++)
#pragma unroll
                for (int q = 0; q < 4; q++) d[mt][nt][q] = 0.f;

        dbgemm<NT, WBLO>(d, xg, m0, XW, cs_a, 64, Wbhg, Wblg, XW + 64,
                         asb, whb, wlb, tid, lane, Rm, Cn);

#pragma unroll
        for (int mt = 0; mt < 2; mt++) {
#pragma unroll
            for (int nt = 0; nt < NT; nt++) {
                int col = Cn + nt * 8 + tg * 2;
                float bx = bb[col], by = bb[col + 1];
                int r0 = m0 + Rm + mt * 16 + gid;
                int r1 = r0 + 8;
                float v0 = gelu_f(d[mt][nt][0] + bx), v1 = gelu_f(d[mt][nt][1] + by);
                float v2 = gelu_f(d[mt][nt][2] + bx), v3 = gelu_f(d[mt][nt][3] + by);
                if (r0 < N_NODES)
                    *(__half2*)(C16 + (size_t)r0 * OS + col) = __floats2half2_rn(v0, v1);
                if (r1 < N_NODES)
                    *(__half2*)(C16 + (size_t)r1 * OS + col) = __floats2half2_rn(v2, v3);
            }
        }
    }
}

// ---------------- L4 GEMM: out = a16 @ W4 + b4 (fp32 out) ----------------
__global__ void __launch_bounds__(256) tgemm16_k(
    const __half* __restrict__ Ag,
    const __half* __restrict__ Whg, const __half* __restrict__ Wlg,
    const float* __restrict__ bias, float* __restrict__ C) {
    __shared__ __half As[2][128][AST];
    __shared__ __half Wh[2][64][AST];
    __shared__ __half Wl[2][64][AST];

    int tid = threadIdx.x;
    int lane = tid & 31, wid = tid >> 5;
    int gid = lane >> 2, tg = lane & 3;
    int warp_m = wid & 3, warp_n = wid >> 2;
    int Rm = warp_m * 32;
    int Cn = warp_n * 32;
    int m0 = blockIdx.x * 128;

    uint32_t asb[2] = { smaddr(&As[0][0][0]), smaddr(&As[1][0][0]) };
    uint32_t whb[2] = { smaddr(&Wh[0][0][0]), smaddr(&Wh[1][0][0]) };
    uint32_t wlb[2] = { smaddr(&Wl[0][0][0]), smaddr(&Wl[1][0][0]) };

    float d[2][4][4];
#pragma unroll
    for (int mt = 0; mt < 2; mt++)
#pragma unroll
        for (int nt = 0; nt < 4; nt++)
#pragma unroll
            for (int q = 0; q < 4; q++) d[mt][nt][q] = 0.f;

    dbgemm<4, true>(d, Ag, m0, 128, 0u, 0, Whg, Wlg, 128, asb, whb, wlb,
                    tid, lane, Rm, Cn);

#pragma unroll
    for (int mt = 0; mt < 2; mt++) {
#pragma unroll
        for (int nt = 0; nt < 4; nt++) {
            int col = Cn + nt * 8 + tg * 2;
            float bx = bias[col], by = bias[col + 1];
            int r0 = m0 + Rm + mt * 16 + gid;
            int r1 = r0 + 8;
            if (r0 < N_NODES)
                *(float2*)(C + (size_t)r0 * 64 + col) =
                    make_float2(d[mt][nt][0] + bx, d[mt][nt][1] + by);
            if (r1 < N_NODES)
                *(float2*)(C + (size_t)r1 * 64 + col) =
                    make_float2(d[mt][nt][2] + bx, d[mt][nt][3] + by);
        }
    }
}

// ---------------- host launcher ----------------
extern "C" void kernel_launch(void* const* d_in, const int* in_sizes, int n_in,
                              void* d_out, int out_size) {
    const float* x     = (const float*)d_in[0];
    const void*  ei    = d_in[1];
    const float* gamma = (const float*)d_in[2];
    const float* beta  = (const float*)d_in[3];
    const float* W1 = (const float*)d_in[4];  const float* b1  = (const float*)d_in[5];
    const float* T1 = (const float*)d_in[6];  const float* t1b = (const float*)d_in[7];
    const float* W2 = (const float*)d_in[8];  const float* b2  = (const float*)d_in[9];
    const float* T2 = (const float*)d_in[10]; const float* t2b = (const float*)d_in[11];
    const float* W3 = (const float*)d_in[12]; const float* b3  = (const float*)d_in[13];
    const float* W4 = (const float*)d_in[14]; const float* b4  = (const float*)d_in[15];
    float* out = (float*)d_out;

    __half *x16, *a16, *act, *wthi, *wtlo;
    cudaGetSymbolAddress((void**)&x16,  g_x16);
    cudaGetSymbolAddress((void**)&a16,  g_a16);
    cudaGetSymbolAddress((void**)&act,  g_act);
    cudaGetSymbolAddress((void**)&wthi, g_wthi);
    cudaGetSymbolAddress((void**)&wtlo, g_wtlo);

    const int OT1 = 8192, OW2 = 24576, OT2 = 28672, OW3 = 45056, OW4 = 69632;

    const int EB = (N_EDGES + 255) / 256;
    const int NB = (N_NODES + 255) / 256;   // 391
    const int GB = (N_NODES + 127) / 128;   // 782
    const int PB = N_NODES / 32;            // 3125 (4 nodes/warp, 8 warps/block)

    const int SM_C1 = 38912 + 64  * AST * 2 * 4;  // 59392
    const int SM_C2 = 38912 + 128 * AST * 2 * 4;  // 79872
    cudaFuncSetAttribute((const void*)chain_k<0, 64, 256, false>,
                         cudaFuncAttributeMaxDynamicSharedMemorySize, SM_C1);
    cudaFuncSetAttribute((const void*)chain_k<128, 128, 128, true>,
                         cudaFuncAttributeMaxDynamicSharedMemorySize, SM_C2);

    // fork: weights/BN/L1 on s1, graph preprocessing on stream 0
    cudaStream_t s1;
    cudaStreamCreateWithFlags(&s1, cudaStreamNonBlocking);
    cudaEvent_t e0, e1;
    cudaEventCreateWithFlags(&e0, cudaEventDisableTiming);
    cudaEventCreateWithFlags(&e1, cudaEventDisableTiming);
    cudaEventRecord(e0, 0);
    cudaStreamWaitEvent(s1, e0, 0);

    // ---- stream s1: weight pre-split + BN zero, BN stats, BN fold, L1 GEMM ----
    prepw_all_k<<<305, 256, 0, s1>>>(T1, W2, T2, W3, W4, wthi, wtlo);
    bn_stats_k<<<512, 256, 0, s1>>>(x);
    bn_fold_k<<<33, 256, 0, s1>>>(gamma, beta, W1, b1, wthi, wtlo);
    tgemm_l1_k<<<GB, 256, 0, s1>>>(x16, wthi, wtlo, act);
    cudaEventRecord(e1, s1);

    // ---- stream 0: graph preprocessing ----
    zero_detect_k<<<NB, 256>>>((const int*)ei);
    deg_k<<<EB, 256>>>(ei);
    blkred_dis_k<<<NB, 256>>>();
    partscan_k<<<1, 512>>>(NB);
    blkscan_k<<<NB, 256>>>();
    csrfill_k<<<EB, 256>>>(ei);

    cudaStreamWaitEvent(0, e1, 0);   // join: props need CSR + h

    // ---- TAGConv1: props fill segs 1..3, then chain (TAG1 + L2) -> h in seg0 ----
    prop_k<<<PB, 256>>>(act,       act + 64);
    prop_k<<<PB, 256>>>(act + 64,  act + 128);
    prop_k<<<PB, 256>>>(act + 128, act + 192);
    chain_k<0, 64, 256, false><<<GB, 256, SM_C1>>>(
        act, wthi + OT1, t1b, nullptr, wthi + OW2, wtlo + OW2, b2, act);

    // ---- TAGConv2: props, then chain (TAG2 + L3 concat x16) -> a16 ----
    prop_k<<<PB, 256>>>(act,       act + 64);
    prop_k<<<PB, 256>>>(act + 64,  act + 128);
    prop_k<<<PB, 256>>>(act + 128, act + 192);
    chain_k<128, 128, 128, true><<<GB, 256, SM_C2>>>(
        act, wthi + OT2, t2b, x16, wthi + OW3, wtlo + OW3, b3, a16);

    // ---- layer 4 ----
    tgemm16_k<<<GB, 256>>>(a16, wthi + OW4, wtlo + OW4, b4, out);
}

// round 14
// speedup vs baseline: 1.1296x; 1.0412x over previous
#include <cuda_runtime.h>
#include <cuda_fp16.h>
#include <math.h>
#include <stdint.h>

#define N_NODES 100000
#define N_EDGES 1000000
#define AST 40   // A/W tile half stride (ldmatrix conflict-free, 16B-aligned rows)
#define CST 72   // Cs half stride

// ---------------- device scratch ----------------
__device__ int   g_is64;
__device__ __align__(16) int   g_degi[N_NODES];
__device__ __align__(16) float g_dis[N_NODES];
__device__ __align__(16) int   g_rowptr[N_NODES + 1];
__device__ __align__(16) int   g_fill[N_NODES];
__device__ __align__(16) int2  g_cw[N_EDGES];
__device__ __align__(16) int   g_part[512];
__device__ __align__(16) float g_bnsum[128];
__device__ __align__(16) float g_bnsq[128];
__device__ __align__(16) float g_b1f[64];     // folded bias: b1 + t @ W1
__device__ __align__(16) __half g_x16[N_NODES * 128];
__device__ __align__(16) __half g_a16[N_NODES * 128];
// unified activation buffer: cols [0,64)=h [64,128)=Ah [128,192)=A2h [192,256)=A3h
__device__ __align__(16) __half g_act[N_NODES * 256];
// pre-split transposed weights: hi/lo fp16, [N][K] k-major
// W1(scaled)=0(8192) T1=8192 W2=24576 T2=28672 W3=45056 W4=69632
__device__ __align__(16) __half g_wthi[77824];
__device__ __align__(16) __half g_wtlo[77824];

// ---------------- helpers ----------------
__device__ __forceinline__ float gelu_f(float v) {
    return 0.5f * v * (1.0f + erff(v * 0.70710678118654752440f));
}

__device__ __forceinline__ void mmaf16(float d[4], const uint32_t a[4],
                                       uint32_t b0, uint32_t b1) {
    asm volatile(
        "mma.sync.aligned.m16n8k16.row.col.f32.f16.f16.f32 "
        "{%0,%1,%2,%3}, {%4,%5,%6,%7}, {%8,%9}, {%0,%1,%2,%3};"
        : "+f"(d[0]), "+f"(d[1]), "+f"(d[2]), "+f"(d[3])
        : "r"(a[0]), "r"(a[1]), "r"(a[2]), "r"(a[3]), "r"(b0), "r"(b1));
}

__device__ __forceinline__ void ldsm_x4(uint32_t r[4], uint32_t a) {
    asm volatile("ldmatrix.sync.aligned.m8n8.x4.shared.b16 {%0,%1,%2,%3}, [%4];"
        : "=r"(r[0]), "=r"(r[1]), "=r"(r[2]), "=r"(r[3]) : "r"(a));
}

__device__ __forceinline__ uint32_t smaddr(const void* p) {
    return (uint32_t)__cvta_generic_to_shared(p);
}

__device__ __forceinline__ void cpa16(uint32_t dst, const void* src, bool p) {
    int sz = p ? 16 : 0;
    asm volatile("cp.async.cg.shared.global [%0], [%1], 16, %2;"
        :: "r"(dst), "l"(src), "r"(sz));
}
__device__ __forceinline__ void cpcommit() { asm volatile("cp.async.commit_group;"); }
__device__ __forceinline__ void cpwait1()  { asm volatile("cp.async.wait_group 1;"); }
__device__ __forceinline__ void cpwait0()  { asm volatile("cp.async.wait_group 0;"); }

// one 32-K step of mma with ldmatrix fragments; WLO = use lo-half of W split
template <int NT, bool WLO>
__device__ __forceinline__ void mma_tile_l(
    float d[2][NT][4], uint32_t Ab_addr, int astr,
    uint32_t Wh_addr, uint32_t Wl_addr,
    int Rm, int Cn, int lane) {
#pragma unroll
    for (int ks = 0; ks < 2; ks++) {
        int kk = ks * 16;
        uint32_t a[2][4];
#pragma unroll
        for (int mt = 0; mt < 2; mt++) {
            int row = Rm + 16 * mt + (lane & 15);
            int kof = kk + 8 * (lane >> 4);
            ldsm_x4(a[mt], Ab_addr + ((row * astr + kof) << 1));
        }
        uint32_t bh[NT / 2][4], bl[NT / 2][4];
#pragma unroll
        for (int q = 0; q < NT / 2; q++) {
            int row = Cn + q * 16 + (lane & 7) + ((lane >> 4) << 3);
            int kof = kk + 8 * ((lane >> 3) & 1);
            uint32_t off = (uint32_t)((row * AST + kof) << 1);
            ldsm_x4(bh[q], Wh_addr + off);
            if (WLO) ldsm_x4(bl[q], Wl_addr + off);
        }
#pragma unroll
        for (int q = 0; q < NT / 2; q++) {
#pragma unroll
            for (int h = 0; h < 2; h++) {
                int nt = q * 2 + h;
#pragma unroll
                for (int mt = 0; mt < 2; mt++) {
                    mmaf16(d[mt][nt], a[mt], bh[q][2 * h], bh[q][2 * h + 1]);
                    if (WLO) mmaf16(d[mt][nt], a[mt], bl[q][2 * h], bl[q][2 * h + 1]);
                }
            }
        }
    }
}

// A tile cp.async: 128 rows x 32 halfs from contiguous fp16 [.][KX]
__device__ __forceinline__ void loadA_cp(uint32_t asbuf, const __half* Ag,
                                         int m0, int KX, int k0, int tid) {
#pragma unroll
    for (int i = 0; i < 2; i++) {
        int idx = i * 256 + tid;
        int r = idx >> 2;
        int c8 = (idx & 3) * 8;
        int gr = m0 + r;
        bool p = gr < N_NODES;
        int rr = p ? gr : (N_NODES - 1);
        cpa16(asbuf + r * (AST * 2) + c8 * 2,
              Ag + (size_t)rr * KX + k0 + c8, p);
    }
}

// W tile cp.async: N2 rows x 32 halfs from [N2][Wstride] (hi, and lo if WLO)
template <int N2, bool WLO>
__device__ __forceinline__ void loadW_cp(uint32_t wh, uint32_t wl,
                                         const __half* Whg, const __half* Wlg,
                                         int Wstride, int k0, int tid) {
#pragma unroll
    for (int i = 0; i < N2 / 64; i++) {
        int idx = i * 256 + tid;
        int r = idx >> 2;
        int c8 = (idx & 3) * 8;
        uint32_t off = (uint32_t)(r * (AST * 2) + c8 * 2);
        cpa16(wh + off, Whg + (size_t)r * Wstride + k0 + c8, true);
        if (WLO) cpa16(wl + off, Wlg + (size_t)r * Wstride + k0 + c8, true);
    }
}

// double-buffered GEMM core: KX halfs from global contiguous A, then KC from Cs smem.
// W rows live in an array of row-stride Wstride halfs (>= KX+KC).
template <int NT, bool WLO>
__device__ __forceinline__ void dbgemm(
    float d[2][NT][4],
    const __half* __restrict__ Ag, int m0, int KX,
    uint32_t cs_addr, int KC,
    const __half* __restrict__ Whg, const __half* __restrict__ Wlg, int Wstride,
    const uint32_t asb[2], const uint32_t whb[2], const uint32_t wlb[2],
    int tid, int lane, int Rm, int Cn) {
    const int Kfull = KX + KC;
    const int NTILES = Kfull / 32;
    // prologue
    if (KX > 0) loadA_cp(asb[0], Ag, m0, KX, 0, tid);
    loadW_cp<NT * 16, WLO>(whb[0], wlb[0], Whg, Wlg, Wstride, 0, tid);
    cpcommit();
    for (int t = 0; t < NTILES; t++) {
        if (t + 1 < NTILES) {
            int k1 = (t + 1) * 32;
            int nb = (t + 1) & 1;
            if (k1 < KX) loadA_cp(asb[nb], Ag, m0, KX, k1, tid);
            loadW_cp<NT * 16, WLO>(whb[nb], wlb[nb], Whg, Wlg, Wstride, k1, tid);
            cpcommit();
            cpwait1();
        } else {
            cpwait0();
        }
        __syncthreads();
        int k0 = t * 32;
        uint32_t Aaddr;
        int astr;
        if (k0 < KX) { Aaddr = asb[t & 1]; astr = AST; }
        else         { Aaddr = cs_addr + ((k0 - KX) << 1); astr = CST; }
        mma_tile_l<NT, WLO>(d, Aaddr, astr, whb[t & 1], wlb[t & 1], Rm, Cn, lane);
        __syncthreads();
    }
}

// ---------------- preprocessing ----------------
// zero degrees + (block 0) detect edge_index dtype
__global__ void zero_detect_k(const int* __restrict__ ei) {
    int i = blockIdx.x * 256 + threadIdx.x;
    if (i < N_NODES) g_degi[i] = 0;
    if (blockIdx.x == 0) {
        __shared__ int anynz;
        if (threadIdx.x == 0) anynz = 0;
        __syncthreads();
        if (ei[threadIdx.x * 2 + 1] != 0) anynz = 1;
        __syncthreads();
        if (threadIdx.x == 0) g_is64 = (anynz == 0) ? 1 : 0;
    }
}

// degree count straight from edge_index dst half
__global__ void deg_k(const void* __restrict__ ei) {
    int e = blockIdx.x * 256 + threadIdx.x;
    if (e >= N_EDGES) return;
    int d = g_is64 ? (int)((const long long*)ei)[N_EDGES + e]
                   : ((const int*)ei)[N_EDGES + e];
    atomicAdd(&g_degi[d], 1);
}

// weight matrices T1,W2,T2,W3,W4 pre-split (W1 handled after BN) + BN zero
__global__ void prepw_all_k(const float* __restrict__ T1,
                            const float* __restrict__ W2, const float* __restrict__ T2,
                            const float* __restrict__ W3, const float* __restrict__ W4,
                            __half* __restrict__ hi, __half* __restrict__ lo) {
    int idx = blockIdx.x * 256 + threadIdx.x;
    if (idx >= 77824) {
        int z = idx - 77824;
        if (z < 128)      g_bnsum[z] = 0.f;
        else if (z < 256) g_bnsq[z - 128] = 0.f;
        return;
    }
    if (idx < 8192) return;  // W1 region filled by bn_fold_k
    const float* src; int base, K, N;
    if (idx < 24576)      { src = T1; base = 8192;  K = 256; N = 64;  }
    else if (idx < 28672) { src = W2; base = 24576; K = 64;  N = 64;  }
    else if (idx < 45056) { src = T2; base = 28672; K = 256; N = 64;  }
    else if (idx < 69632) { src = W3; base = 45056; K = 192; N = 128; }
    else                  { src = W4; base = 69632; K = 128; N = 64;  }
    int r = idx - base;
    int k = r / N, n = r - k * N;
    float w = src[r];
    __half h = __float2half_rn(w);
    hi[base + n * K + k] = h;
    lo[base + n * K + k] = __float2half_rn(w - __half2float(h));
}

// block reduce of degrees + dis computation (fused)
__global__ void blkred_dis_k() {
    __shared__ int ws[8];
    int i = blockIdx.x * 256 + threadIdx.x;
    int v = (i < N_NODES) ? g_degi[i] : 0;
    if (i < N_NODES) g_dis[i] = (v > 0) ? rsqrtf((float)v) : 0.f;
    int s = v;
#pragma unroll
    for (int o = 16; o; o >>= 1) s += __shfl_down_sync(0xffffffffu, s, o);
    if ((threadIdx.x & 31) == 0) ws[threadIdx.x >> 5] = s;
    __syncthreads();
    if (threadIdx.x < 8) {
        int t = ws[threadIdx.x];
#pragma unroll
        for (int o = 4; o; o >>= 1) t += __shfl_down_sync(0xffu, t, o);
        if (threadIdx.x == 0) g_part[blockIdx.x] = t;
    }
}

__global__ void partscan_k(int nb) {
    __shared__ int ws[16];
    int t = threadIdx.x, lane = t & 31, w = t >> 5;
    int v = (t < nb) ? g_part[t] : 0;
    int x = v;
#pragma unroll
    for (int o = 1; o < 32; o <<= 1) {
        int y = __shfl_up_sync(0xffffffffu, x, o);
        if (lane >= o) x += y;
    }
    if (lane == 31) ws[w] = x;
    __syncthreads();
    if (w == 0 && lane < 16) {
        int s = ws[lane];
#pragma unroll
        for (int o = 1; o < 16; o <<= 1) {
            int y = __shfl_up_sync(0x0000ffffu, s, o);
            if (lane >= o) s += y;
        }
        ws[lane] = s;
    }
    __syncthreads();
    int pre = (w ? ws[w - 1] : 0) + x - v;
    if (t < nb) g_part[t] = pre;
    if (t == nb - 1) g_rowptr[N_NODES] = pre + v;
}

__global__ void blkscan_k() {
    __shared__ int ws[8];
    int t = threadIdx.x, lane = t & 31, w = t >> 5;
    int i = blockIdx.x * 256 + t;
    int v = (i < N_NODES) ? g_degi[i] : 0;
    int x = v;
#pragma unroll
    for (int o = 1; o < 32; o <<= 1) {
        int y = __shfl_up_sync(0xffffffffu, x, o);
        if (lane >= o) x += y;
    }
    if (lane == 31) ws[w] = x;
    __syncthreads();
    if (w == 0 && lane < 8) {
        int s = ws[lane];
#pragma unroll
        for (int o = 1; o < 8; o <<= 1) {
            int y = __shfl_up_sync(0x000000ffu, s, o);
            if (lane >= o) s += y;
        }
        ws[lane] = s;
    }
    __syncthreads();
    int ex = g_part[blockIdx.x] + (w ? ws[w - 1] : 0) + x - v;
    if (i < N_NODES) { g_rowptr[i] = ex; g_fill[i] = ex; }
}

// CSR fill straight from edge_index
__global__ void csrfill_k(const void* __restrict__ ei) {
    int e = blockIdx.x * 256 + threadIdx.x;
    if (e >= N_EDGES) return;
    int s, d;
    if (g_is64) {
        const long long* p = (const long long*)ei;
        s = (int)p[e];
        d = (int)p[N_EDGES + e];
    } else {
        const int* p = (const int*)ei;
        s = p[e];
        d = p[N_EDGES + e];
    }
    int pos = atomicAdd(&g_fill[d], 1);
    g_cw[pos] = make_int2(s, __float_as_int(g_dis[s] * g_dis[d]));
}

__global__ void bn_stats_k(const float* __restrict__ x) {
    int col = threadIdx.x & 127;
    int r = blockIdx.x * 2 + (threadIdx.x >> 7);
    float s = 0.f, q = 0.f;
    for (; r < N_NODES; r += gridDim.x * 2) {
        float v = x[(size_t)r * 128 + col];
        g_x16[(size_t)r * 128 + col] = __float2half_rn(v);
        s += v;
        q += v * v;
    }
    atomicAdd(&g_bnsum[col], s);
    atomicAdd(&g_bnsq[col], q);
}

// BN fold: blocks 0..31 split BN-scaled W1; block 32 folds bias b1' = b1 + t@W1
__global__ void bn_fold_k(const float* __restrict__ gamma, const float* __restrict__ beta,
                          const float* __restrict__ W1, const float* __restrict__ b1,
                          __half* __restrict__ hi, __half* __restrict__ lo) {
    int b = blockIdx.x, t = threadIdx.x;
    if (b < 32) {
        int idx = b * 256 + t;           // < 8192
        int k = idx >> 6, n = idx & 63;
        float mean = g_bnsum[k] * (1.0f / N_NODES);
        float var  = g_bnsq[k] * (1.0f / N_NODES) - mean * mean;
        float s = gamma[k] * rsqrtf(var + 1e-5f);
        float w = W1[idx] * s;
        __half h = __float2half_rn(w);
        hi[n * 128 + k] = h;
        lo[n * 128 + k] = __float2half_rn(w - __half2float(h));
    } else {
        __shared__ float ts[128];
        if (t < 128) {
            float mean = g_bnsum[t] * (1.0f / N_NODES);
            float var  = g_bnsq[t] * (1.0f / N_NODES) - mean * mean;
            float s = gamma[t] * rsqrtf(var + 1e-5f);
            ts[t] = beta[t] - mean * s;
        }
        __syncthreads();
        if (t < 64) {
            float acc = b1[t];
            for (int k = 0; k < 128; k++)
                acc += ts[k] * W1[k * 64 + t];
            g_b1f[t] = acc;
        }
    }
}

// CSR propagation on g_act segments: 4 nodes/warp, 8 lanes x uint4 per row.
__global__ void __launch_bounds__(256) prop_k(const __half* __restrict__ in,
                                              __half* __restrict__ out) {
    int w = blockIdx.x * 8 + (threadIdx.x >> 5);
    int lane = threadIdx.x & 31;
    int node = (w << 2) + (lane >> 3);
    int li = lane & 7;
    int beg = g_rowptr[node], end = g_rowptr[node + 1];
    float a0 = 0.f, a1 = 0.f, a2 = 0.f, a3 = 0.f;
    float a4 = 0.f, a5 = 0.f, a6 = 0.f, a7 = 0.f;
    int e = beg;
    while (__any_sync(0xffffffffu, e < end)) {
#pragma unroll
        for (int u = 0; u < 4; u++) {
            int ee = min(e + u, N_EDGES - 1);
            int2 c = __ldg(g_cw + ee);
            float wv = (e + u < end) ? __int_as_float(c.y) : 0.f;
            uint4 r = __ldg((const uint4*)(in + (size_t)c.x * 256) + li);
            float2 f0 = __half22float2(*(__half2*)&r.x);
            float2 f1 = __half22float2(*(__half2*)&r.y);
            float2 f2 = __half22float2(*(__half2*)&r.z);
            float2 f3 = __half22float2(*(__half2*)&r.w);
            a0 = fmaf(wv, f0.x, a0);
            a1 = fmaf(wv, f0.y, a1);
            a2 = fmaf(wv, f1.x, a2);
            a3 = fmaf(wv, f1.y, a3);
            a4 = fmaf(wv, f2.x, a4);
            a5 = fmaf(wv, f2.y, a5);
            a6 = fmaf(wv, f3.x, a6);
            a7 = fmaf(wv, f3.y, a7);
        }
        e += 4;
    }
    __half2 o0 = __floats2half2_rn(a0, a1);
    __half2 o1 = __floats2half2_rn(a2, a3);
    __half2 o2 = __floats2half2_rn(a4, a5);
    __half2 o3 = __floats2half2_rn(a6, a7);
    uint4 uo = make_uint4(*(uint32_t*)&o0, *(uint32_t*)&o1,
                          *(uint32_t*)&o2, *(uint32_t*)&o3);
    *((uint4*)(out + (size_t)node * 256) + li) = uo;
}

// ---------------- L1 GEMM: h = gelu(x16 @ W1' + b1') -> g_act seg0 ----------------
__global__ void __launch_bounds__(256, 4) tgemm_l1_k(
    const __half* __restrict__ Ag,
    const __half* __restrict__ Whg, const __half* __restrict__ Wlg,
    __half* __restrict__ Cact) {
    __shared__ __half As[2][128][AST];
    __shared__ __half Wh[2][64][AST];
    __shared__ __half Wl[2][64][AST];

    int tid = threadIdx.x;
    int lane = tid & 31, wid = tid >> 5;
    int gid = lane >> 2, tg = lane & 3;
    int warp_m = wid & 3, warp_n = wid >> 2;
    int Rm = warp_m * 32;
    int Cn = warp_n * 32;
    int m0 = blockIdx.x * 128;

    uint32_t asb[2] = { smaddr(&As[0][0][0]), smaddr(&As[1][0][0]) };
    uint32_t whb[2] = { smaddr(&Wh[0][0][0]), smaddr(&Wh[1][0][0]) };
    uint32_t wlb[2] = { smaddr(&Wl[0][0][0]), smaddr(&Wl[1][0][0]) };

    float d[2][4][4];
#pragma unroll
    for (int mt = 0; mt < 2; mt++)
#pragma unroll
        for (int nt = 0; nt < 4; nt++)
#pragma unroll
            for (int q = 0; q < 4; q++) d[mt][nt][q] = 0.f;

    dbgemm<4, true>(d, Ag, m0, 128, 0u, 0, Whg, Wlg, 128, asb, whb, wlb,
                    tid, lane, Rm, Cn);

#pragma unroll
    for (int mt = 0; mt < 2; mt++) {
#pragma unroll
        for (int nt = 0; nt < 4; nt++) {
            int col = Cn + nt * 8 + tg * 2;
            float bx = g_b1f[col], by = g_b1f[col + 1];
            int r0 = m0 + Rm + mt * 16 + gid;
            int r1 = r0 + 8;
            float v0 = gelu_f(d[mt][nt][0] + bx), v1 = gelu_f(d[mt][nt][1] + by);
            float v2 = gelu_f(d[mt][nt][2] + bx), v3 = gelu_f(d[mt][nt][3] + by);
            if (r0 < N_NODES)
                *(__half2*)(Cact + (size_t)r0 * 256 + col) = __floats2half2_rn(v0, v1);
            if (r1 < N_NODES)
                *(__half2*)(Cact + (size_t)r1 * 256 + col) = __floats2half2_rn(v2, v3);
        }
    }
}

// ---------------- fused 2-stage chain GEMM ----------------
// stage1 (hi-only W): Cs = gelu(g_act[128 rows][256] @ Wa + ba), N=64 (smem)
// stage2: out = gelu(concat(xg[XW], Cs) @ Wb + bb), N2 -> fp16 global stride OS
// WB row stride = XW + 64; WBLO selects hi-only vs hi/lo for Wb.
// smem W region: 2 buffers if hi-only, 4 if hi+lo.
template <int XW, int N2, int OS, bool WBLO>
__global__ void __launch_bounds__(256) chain_k(
    const __half* __restrict__ act,
    const __half* __restrict__ Wahg,
    const float* __restrict__ ba,
    const __half* __restrict__ xg,
    const __half* __restrict__ Wbhg, const __half* __restrict__ Wblg,
    const float* __restrict__ bb,
    __half* __restrict__ C16) {
    constexpr int NW = (N2 > 64) ? N2 : 64;
    constexpr uint32_t WSZ = NW * AST * 2;
    extern __shared__ char sm[];
    // layout: As0 As1 | Cs | W buffers
    uint32_t sbase = smaddr(sm);
    uint32_t asb[2] = { sbase, sbase + 10240 };
    uint32_t cs_a   = sbase + 20480;
    uint32_t wbase  = sbase + 38912;
    uint32_t whb[2], wlb[2];
    if (WBLO) {
        whb[0] = wbase;           whb[1] = wbase + 2 * WSZ;
        wlb[0] = wbase + WSZ;     wlb[1] = wbase + 3 * WSZ;
    } else {
        whb[0] = wbase;           whb[1] = wbase + WSZ;
        wlb[0] = wbase;           wlb[1] = wbase + WSZ;   // unused
    }
    __half (*Cs)[CST] = (__half(*)[CST])(sm + 20480);

    int tid = threadIdx.x;
    int lane = tid & 31, wid = tid >> 5;
    int gid = lane >> 2, tg = lane & 3;
    int warp_m = wid & 3, warp_n = wid >> 2;
    int Rm = warp_m * 32;
    int m0 = blockIdx.x * 128;

    // -------- stage 1: K=256 from g_act, N=64, hi-only weights --------
    {
        int Cn = warp_n * 32;
        float d[2][4][4];
#pragma unroll
        for (int mt = 0; mt < 2; mt++)
#pragma unroll
            for (int nt = 0; nt < 4; nt++)
#pragma unroll
                for (int q = 0; q < 4; q++) d[mt][nt][q] = 0.f;

        dbgemm<4, false>(d, act, m0, 256, 0u, 0, Wahg, Wahg, 256, asb, whb, wlb,
                         tid, lane, Rm, Cn);

#pragma unroll
        for (int mt = 0; mt < 2; mt++) {
#pragma unroll
            for (int nt = 0; nt < 4; nt++) {
                int col = Cn + nt * 8 + tg * 2;
                float bx = ba[col], by = ba[col + 1];
                int r0 = Rm + mt * 16 + gid;
                *(__half2*)&Cs[r0][col] =
                    __floats2half2_rn(gelu_f(d[mt][nt][0] + bx), gelu_f(d[mt][nt][1] + by));
                *(__half2*)&Cs[r0 + 8][col] =
                    __floats2half2_rn(gelu_f(d[mt][nt][2] + bx), gelu_f(d[mt][nt][3] + by));
            }
        }
    }
    __syncthreads();

    // -------- stage 2: K = XW (global x16) + 64 (Cs), N = N2 --------
    {
        constexpr int NT = N2 / 16;
        int Cn = warp_n * (N2 / 2);
        float d[2][NT][4];
#pragma unroll
        for (int mt = 0; mt < 2; mt++)
#pragma unroll
            for (int nt = 0; nt < NT; nt++)
#pragma unroll
                for (int q = 0; q < 4; q++) d[mt][nt][q] = 0.f;

        dbgemm<NT, WBLO>(d, xg, m0, XW, cs_a, 64, Wbhg, Wblg, XW + 64,
                         asb, whb, wlb, tid, lane, Rm, Cn);

#pragma unroll
        for (int mt = 0; mt < 2; mt++) {
#pragma unroll
            for (int nt = 0; nt < NT; nt++) {
                int col = Cn + nt * 8 + tg * 2;
                float bx = bb[col], by = bb[col + 1];
                int r0 = m0 + Rm + mt * 16 + gid;
                int r1 = r0 + 8;
                float v0 = gelu_f(d[mt][nt][0] + bx), v1 = gelu_f(d[mt][nt][1] + by);
                float v2 = gelu_f(d[mt][nt][2] + bx), v3 = gelu_f(d[mt][nt][3] + by);
                if (r0 < N_NODES)
                    *(__half2*)(C16 + (size_t)r0 * OS + col) = __floats2half2_rn(v0, v1);
                if (r1 < N_NODES)
                    *(__half2*)(C16 + (size_t)r1 * OS + col) = __floats2half2_rn(v2, v3);
            }
        }
    }
}

// ---------------- L4 GEMM: out = a16 @ W4 + b4 (fp32 out) ----------------
__global__ void __launch_bounds__(256, 4) tgemm16_k(
    const __half* __restrict__ Ag,
    const __half* __restrict__ Whg, const __half* __restrict__ Wlg,
    const float* __restrict__ bias, float* __restrict__ C) {
    __shared__ __half As[2][128][AST];
    __shared__ __half Wh[2][64][AST];
    __shared__ __half Wl[2][64][AST];

    int tid = threadIdx.x;
    int lane = tid & 31, wid = tid >> 5;
    int gid = lane >> 2, tg = lane & 3;
    int warp_m = wid & 3, warp_n = wid >> 2;
    int Rm = warp_m * 32;
    int Cn = warp_n * 32;
    int m0 = blockIdx.x * 128;

    uint32_t asb[2] = { smaddr(&As[0][0][0]), smaddr(&As[1][0][0]) };
    uint32_t whb[2] = { smaddr(&Wh[0][0][0]), smaddr(&Wh[1][0][0]) };
    uint32_t wlb[2] = { smaddr(&Wl[0][0][0]), smaddr(&Wl[1][0][0]) };

    float d[2][4][4];
#pragma unroll
    for (int mt = 0; mt < 2; mt++)
#pragma unroll
        for (int nt = 0; nt < 4; nt++)
#pragma unroll
            for (int q = 0; q < 4; q++) d[mt][nt][q] = 0.f;

    dbgemm<4, true>(d, Ag, m0, 128, 0u, 0, Whg, Wlg, 128, asb, whb, wlb,
                    tid, lane, Rm, Cn);

#pragma unroll
    for (int mt = 0; mt < 2; mt++) {
#pragma unroll
        for (int nt = 0; nt < 4; nt++) {
            int col = Cn + nt * 8 + tg * 2;
            float bx = bias[col], by = bias[col + 1];
            int r0 = m0 + Rm + mt * 16 + gid;
            int r1 = r0 + 8;
            if (r0 < N_NODES)
                *(float2*)(C + (size_t)r0 * 64 + col) =
                    make_float2(d[mt][nt][0] + bx, d[mt][nt][1] + by);
            if (r1 < N_NODES)
                *(float2*)(C + (size_t)r1 * 64 + col) =
                    make_float2(d[mt][nt][2] + bx, d[mt][nt][3] + by);
        }
    }
}

// ---------------- host launcher ----------------
extern "C" void kernel_launch(void* const* d_in, const int* in_sizes, int n_in,
                              void* d_out, int out_size) {
    const float* x     = (const float*)d_in[0];
    const void*  ei    = d_in[1];
    const float* gamma = (const float*)d_in[2];
    const float* beta  = (const float*)d_in[3];
    const float* W1 = (const float*)d_in[4];  const float* b1  = (const float*)d_in[5];
    const float* T1 = (const float*)d_in[6];  const float* t1b = (const float*)d_in[7];
    const float* W2 = (const float*)d_in[8];  const float* b2  = (const float*)d_in[9];
    const float* T2 = (const float*)d_in[10]; const float* t2b = (const float*)d_in[11];
    const float* W3 = (const float*)d_in[12]; const float* b3  = (const float*)d_in[13];
    const float* W4 = (const float*)d_in[14]; const float* b4  = (const float*)d_in[15];
    float* out = (float*)d_out;

    __half *x16, *a16, *act, *wthi, *wtlo;
    cudaGetSymbolAddress((void**)&x16,  g_x16);
    cudaGetSymbolAddress((void**)&a16,  g_a16);
    cudaGetSymbolAddress((void**)&act,  g_act);
    cudaGetSymbolAddress((void**)&wthi, g_wthi);
    cudaGetSymbolAddress((void**)&wtlo, g_wtlo);

    const int OT1 = 8192, OW2 = 24576, OT2 = 28672, OW3 = 45056, OW4 = 69632;

    const int EB = (N_EDGES + 255) / 256;
    const int NB = (N_NODES + 255) / 256;   // 391
    const int GB = (N_NODES + 127) / 128;   // 782
    const int PB = N_NODES / 32;            // 3125 (4 nodes/warp, 8 warps/block)

    const int SM_C1 = 38912 + 2 * 64  * AST * 2;  // 49152 (hi-only W2)
    const int SM_C2 = 38912 + 2 * 128 * AST * 2;  // 59392 (hi-only W3)
    cudaFuncSetAttribute((const void*)chain_k<0, 64, 256, false>,
                         cudaFuncAttributeMaxDynamicSharedMemorySize, SM_C1);
    cudaFuncSetAttribute((const void*)chain_k<128, 128, 128, false>,
                         cudaFuncAttributeMaxDynamicSharedMemorySize, SM_C2);

    // fork: weights/BN/L1 on s1, graph preprocessing on stream 0
    cudaStream_t s1;
    cudaStreamCreateWithFlags(&s1, cudaStreamNonBlocking);
    cudaEvent_t e0, e1;
    cudaEventCreateWithFlags(&e0, cudaEventDisableTiming);
    cudaEventCreateWithFlags(&e1, cudaEventDisableTiming);
    cudaEventRecord(e0, 0);
    cudaStreamWaitEvent(s1, e0, 0);

    // ---- stream s1: weight pre-split + BN zero, BN stats, BN fold, L1 GEMM ----
    prepw_all_k<<<305, 256, 0, s1>>>(T1, W2, T2, W3, W4, wthi, wtlo);
    bn_stats_k<<<512, 256, 0, s1>>>(x);
    bn_fold_k<<<33, 256, 0, s1>>>(gamma, beta, W1, b1, wthi, wtlo);
    tgemm_l1_k<<<GB, 256, 0, s1>>>(x16, wthi, wtlo, act);
    cudaEventRecord(e1, s1);

    // ---- stream 0: graph preprocessing ----
    zero_detect_k<<<NB, 256>>>((const int*)ei);
    deg_k<<<EB, 256>>>(ei);
    blkred_dis_k<<<NB, 256>>>();
    partscan_k<<<1, 512>>>(NB);
    blkscan_k<<<NB, 256>>>();
    csrfill_k<<<EB, 256>>>(ei);

    cudaStreamWaitEvent(0, e1, 0);   // join: props need CSR + h

    // ---- TAGConv1: props fill segs 1..3, then chain (TAG1 + L2) -> h in seg0 ----
    prop_k<<<PB, 256>>>(act,       act + 64);
    prop_k<<<PB, 256>>>(act + 64,  act + 128);
    prop_k<<<PB, 256>>>(act + 128, act + 192);
    chain_k<0, 64, 256, false><<<GB, 256, SM_C1>>>(
        act, wthi + OT1, t1b, nullptr, wthi + OW2, wtlo + OW2, b2, act);

    // ---- TAGConv2: props, then chain (TAG2 + L3 concat x16) -> a16 ----
    prop_k<<<PB, 256>>>(act,       act + 64);
    prop_k<<<PB, 256>>>(act + 64,  act + 128);
    prop_k<<<PB, 256>>>(act + 128, act + 192);
    chain_k<128, 128, 128, false><<<GB, 256, SM_C2>>>(
        act, wthi + OT2, t2b, x16, wthi + OW3, wtlo + OW3, b3, a16);

    // ---- layer 4 ----
    tgemm16_k<<<GB, 256>>>(a16, wthi + OW4, wtlo + OW4, b4, out);
}

// round 15
// speedup vs baseline: 1.1611x; 1.0280x over previous
#include <cuda_runtime.h>
#include <cuda_fp16.h>
#include <math.h>
#include <stdint.h>

#define N_NODES 100000
#define N_EDGES 1000000
#define AST 40    // A/W tile half stride (ldmatrix conflict-free, 16B-aligned rows)
#define CST 72    // Cs half stride
#define C2ST 136  // stage-2 output tile half stride (128 cols + 8 pad)

// ---------------- device scratch ----------------
__device__ int   g_is64;
__device__ __align__(16) int   g_degi[N_NODES];
__device__ __align__(16) float g_dis[N_NODES];
__device__ __align__(16) int   g_rowptr[N_NODES + 1];
__device__ __align__(16) int   g_fill[N_NODES];
__device__ __align__(16) int2  g_cw[N_EDGES];
__device__ __align__(16) int   g_part[512];
__device__ __align__(16) float g_bnsum[128];
__device__ __align__(16) float g_bnsq[128];
__device__ __align__(16) float g_b1f[64];     // folded bias: b1 + t @ W1
__device__ __align__(16) __half g_x16[N_NODES * 128];
// unified activation buffer: cols [0,64)=h [64,128)=Ah [128,192)=A2h [192,256)=A3h
__device__ __align__(16) __half g_act[N_NODES * 256];
// pre-split transposed weights: hi/lo fp16, [N][K] k-major
// W1(scaled)=0(8192) T1=8192 W2=24576 T2=28672 W3=45056 W4=69632
__device__ __align__(16) __half g_wthi[77824];
__device__ __align__(16) __half g_wtlo[77824];

// ---------------- helpers ----------------
__device__ __forceinline__ float gelu_f(float v) {
    return 0.5f * v * (1.0f + erff(v * 0.70710678118654752440f));
}

__device__ __forceinline__ void mmaf16(float d[4], const uint32_t a[4],
                                       uint32_t b0, uint32_t b1) {
    asm volatile(
        "mma.sync.aligned.m16n8k16.row.col.f32.f16.f16.f32 "
        "{%0,%1,%2,%3}, {%4,%5,%6,%7}, {%8,%9}, {%0,%1,%2,%3};"
        : "+f"(d[0]), "+f"(d[1]), "+f"(d[2]), "+f"(d[3])
        : "r"(a[0]), "r"(a[1]), "r"(a[2]), "r"(a[3]), "r"(b0), "r"(b1));
}

__device__ __forceinline__ void ldsm_x4(uint32_t r[4], uint32_t a) {
    asm volatile("ldmatrix.sync.aligned.m8n8.x4.shared.b16 {%0,%1,%2,%3}, [%4];"
        : "=r"(r[0]), "=r"(r[1]), "=r"(r[2]), "=r"(r[3]) : "r"(a));
}

__device__ __forceinline__ uint32_t smaddr(const void* p) {
    return (uint32_t)__cvta_generic_to_shared(p);
}

__device__ __forceinline__ void cpa16(uint32_t dst, const void* src, bool p) {
    int sz = p ? 16 : 0;
    asm volatile("cp.async.cg.shared.global [%0], [%1], 16, %2;"
        :: "r"(dst), "l"(src), "r"(sz));
}
__device__ __forceinline__ void cpcommit() { asm volatile("cp.async.commit_group;"); }
__device__ __forceinline__ void cpwait1()  { asm volatile("cp.async.wait_group 1;"); }
__device__ __forceinline__ void cpwait0()  { asm volatile("cp.async.wait_group 0;"); }

// one 32-K step of mma with ldmatrix fragments; WLO = use lo-half of W split
template <int NT, bool WLO>
__device__ __forceinline__ void mma_tile_l(
    float d[2][NT][4], uint32_t Ab_addr, int astr,
    uint32_t Wh_addr, uint32_t Wl_addr,
    int Rm, int Cn, int lane) {
#pragma unroll
    for (int ks = 0; ks < 2; ks++) {
        int kk = ks * 16;
        uint32_t a[2][4];
#pragma unroll
        for (int mt = 0; mt < 2; mt++) {
            int row = Rm + 16 * mt + (lane & 15);
            int kof = kk + 8 * (lane >> 4);
            ldsm_x4(a[mt], Ab_addr + ((row * astr + kof) << 1));
        }
        uint32_t bh[NT / 2][4], bl[NT / 2][4];
#pragma unroll
        for (int q = 0; q < NT / 2; q++) {
            int row = Cn + q * 16 + (lane & 7) + ((lane >> 4) << 3);
            int kof = kk + 8 * ((lane >> 3) & 1);
            uint32_t off = (uint32_t)((row * AST + kof) << 1);
            ldsm_x4(bh[q], Wh_addr + off);
            if (WLO) ldsm_x4(bl[q], Wl_addr + off);
        }
#pragma unroll
        for (int q = 0; q < NT / 2; q++) {
#pragma unroll
            for (int h = 0; h < 2; h++) {
                int nt = q * 2 + h;
#pragma unroll
                for (int mt = 0; mt < 2; mt++) {
                    mmaf16(d[mt][nt], a[mt], bh[q][2 * h], bh[q][2 * h + 1]);
                    if (WLO) mmaf16(d[mt][nt], a[mt], bl[q][2 * h], bl[q][2 * h + 1]);
                }
            }
        }
    }
}

// A tile cp.async: 128 rows x 32 halfs from contiguous fp16 [.][KX]
__device__ __forceinline__ void loadA_cp(uint32_t asbuf, const __half* Ag,
                                         int m0, int KX, int k0, int tid) {
#pragma unroll
    for (int i = 0; i < 2; i++) {
        int idx = i * 256 + tid;
        int r = idx >> 2;
        int c8 = (idx & 3) * 8;
        int gr = m0 + r;
        bool p = gr < N_NODES;
        int rr = p ? gr : (N_NODES - 1);
        cpa16(asbuf + r * (AST * 2) + c8 * 2,
              Ag + (size_t)rr * KX + k0 + c8, p);
    }
}

// W tile cp.async: N2 rows x 32 halfs from [N2][Wstride] (hi, and lo if WLO)
template <int N2, bool WLO>
__device__ __forceinline__ void loadW_cp(uint32_t wh, uint32_t wl,
                                         const __half* Whg, const __half* Wlg,
                                         int Wstride, int k0, int tid) {
#pragma unroll
    for (int i = 0; i < N2 / 64; i++) {
        int idx = i * 256 + tid;
        int r = idx >> 2;
        int c8 = (idx & 3) * 8;
        uint32_t off = (uint32_t)(r * (AST * 2) + c8 * 2);
        cpa16(wh + off, Whg + (size_t)r * Wstride + k0 + c8, true);
        if (WLO) cpa16(wl + off, Wlg + (size_t)r * Wstride + k0 + c8, true);
    }
}

// double-buffered GEMM core: KX halfs from global contiguous A, then KC halfs
// from an smem tile at cs_addr with row stride cstr. W row stride = Wstride.
template <int NT, bool WLO>
__device__ __forceinline__ void dbgemm(
    float d[2][NT][4],
    const __half* __restrict__ Ag, int m0, int KX,
    uint32_t cs_addr, int KC, int cstr,
    const __half* __restrict__ Whg, const __half* __restrict__ Wlg, int Wstride,
    const uint32_t asb[2], const uint32_t whb[2], const uint32_t wlb[2],
    int tid, int lane, int Rm, int Cn) {
    const int Kfull = KX + KC;
    const int NTILES = Kfull / 32;
    // prologue
    if (KX > 0) loadA_cp(asb[0], Ag, m0, KX, 0, tid);
    loadW_cp<NT * 16, WLO>(whb[0], wlb[0], Whg, Wlg, Wstride, 0, tid);
    cpcommit();
    for (int t = 0; t < NTILES; t++) {
        if (t + 1 < NTILES) {
            int k1 = (t + 1) * 32;
            int nb = (t + 1) & 1;
            if (k1 < KX) loadA_cp(asb[nb], Ag, m0, KX, k1, tid);
            loadW_cp<NT * 16, WLO>(whb[nb], wlb[nb], Whg, Wlg, Wstride, k1, tid);
            cpcommit();
            cpwait1();
        } else {
            cpwait0();
        }
        __syncthreads();
        int k0 = t * 32;
        uint32_t Aaddr;
        int astr;
        if (k0 < KX) { Aaddr = asb[t & 1]; astr = AST; }
        else         { Aaddr = cs_addr + ((k0 - KX) << 1); astr = cstr; }
        mma_tile_l<NT, WLO>(d, Aaddr, astr, whb[t & 1], wlb[t & 1], Rm, Cn, lane);
        __syncthreads();
    }
}

// ---------------- preprocessing ----------------
__global__ void zero_detect_k(const int* __restrict__ ei) {
    int i = blockIdx.x * 256 + threadIdx.x;
    if (i < N_NODES) g_degi[i] = 0;
    if (blockIdx.x == 0) {
        __shared__ int anynz;
        if (threadIdx.x == 0) anynz = 0;
        __syncthreads();
        if (ei[threadIdx.x * 2 + 1] != 0) anynz = 1;
        __syncthreads();
        if (threadIdx.x == 0) g_is64 = (anynz == 0) ? 1 : 0;
    }
}

__global__ void deg_k(const void* __restrict__ ei) {
    int e = blockIdx.x * 256 + threadIdx.x;
    if (e >= N_EDGES) return;
    int d = g_is64 ? (int)((const long long*)ei)[N_EDGES + e]
                   : ((const int*)ei)[N_EDGES + e];
    atomicAdd(&g_degi[d], 1);
}

__global__ void prepw_all_k(const float* __restrict__ T1,
                            const float* __restrict__ W2, const float* __restrict__ T2,
                            const float* __restrict__ W3, const float* __restrict__ W4,
                            __half* __restrict__ hi, __half* __restrict__ lo) {
    int idx = blockIdx.x * 256 + threadIdx.x;
    if (idx >= 77824) {
        int z = idx - 77824;
        if (z < 128)      g_bnsum[z] = 0.f;
        else if (z < 256) g_bnsq[z - 128] = 0.f;
        return;
    }
    if (idx < 8192) return;  // W1 region filled by bn_fold_k
    const float* src; int base, K, N;
    if (idx < 24576)      { src = T1; base = 8192;  K = 256; N = 64;  }
    else if (idx < 28672) { src = W2; base = 24576; K = 64;  N = 64;  }
    else if (idx < 45056) { src = T2; base = 28672; K = 256; N = 64;  }
    else if (idx < 69632) { src = W3; base = 45056; K = 192; N = 128; }
    else                  { src = W4; base = 69632; K = 128; N = 64;  }
    int r = idx - base;
    int k = r / N, n = r - k * N;
    float w = src[r];
    __half h = __float2half_rn(w);
    hi[base + n * K + k] = h;
    lo[base + n * K + k] = __float2half_rn(w - __half2float(h));
}

__global__ void blkred_dis_k() {
    __shared__ int ws[8];
    int i = blockIdx.x * 256 + threadIdx.x;
    int v = (i < N_NODES) ? g_degi[i] : 0;
    if (i < N_NODES) g_dis[i] = (v > 0) ? rsqrtf((float)v) : 0.f;
    int s = v;
#pragma unroll
    for (int o = 16; o; o >>= 1) s += __shfl_down_sync(0xffffffffu, s, o);
    if ((threadIdx.x & 31) == 0) ws[threadIdx.x >> 5] = s;
    __syncthreads();
    if (threadIdx.x < 8) {
        int t = ws[threadIdx.x];
#pragma unroll
        for (int o = 4; o; o >>= 1) t += __shfl_down_sync(0xffu, t, o);
        if (threadIdx.x == 0) g_part[blockIdx.x] = t;
    }
}

__global__ void partscan_k(int nb) {
    __shared__ int ws[16];
    int t = threadIdx.x, lane = t & 31, w = t >> 5;
    int v = (t < nb) ? g_part[t] : 0;
    int x = v;
#pragma unroll
    for (int o = 1; o < 32; o <<= 1) {
        int y = __shfl_up_sync(0xffffffffu, x, o);
        if (lane >= o) x += y;
    }
    if (lane == 31) ws[w] = x;
    __syncthreads();
    if (w == 0 && lane < 16) {
        int s = ws[lane];
#pragma unroll
        for (int o = 1; o < 16; o <<= 1) {
            int y = __shfl_up_sync(0x0000ffffu, s, o);
            if (lane >= o) s += y;
        }
        ws[lane] = s;
    }
    __syncthreads();
    int pre = (w ? ws[w - 1] : 0) + x - v;
    if (t < nb) g_part[t] = pre;
    if (t == nb - 1) g_rowptr[N_NODES] = pre + v;
}

__global__ void blkscan_k() {
    __shared__ int ws[8];
    int t = threadIdx.x, lane = t & 31, w = t >> 5;
    int i = blockIdx.x * 256 + t;
    int v = (i < N_NODES) ? g_degi[i] : 0;
    int x = v;
#pragma unroll
    for (int o = 1; o < 32; o <<= 1) {
        int y = __shfl_up_sync(0xffffffffu, x, o);
        if (lane >= o) x += y;
    }
    if (lane == 31) ws[w] = x;
    __syncthreads();
    if (w == 0 && lane < 8) {
        int s = ws[lane];
#pragma unroll
        for (int o = 1; o < 8; o <<= 1) {
            int y = __shfl_up_sync(0x000000ffu, s, o);
            if (lane >= o) s += y;
        }
        ws[lane] = s;
    }
    __syncthreads();
    int ex = g_part[blockIdx.x] + (w ? ws[w - 1] : 0) + x - v;
    if (i < N_NODES) { g_rowptr[i] = ex; g_fill[i] = ex; }
}

__global__ void csrfill_k(const void* __restrict__ ei) {
    int e = blockIdx.x * 256 + threadIdx.x;
    if (e >= N_EDGES) return;
    int s, d;
    if (g_is64) {
        const long long* p = (const long long*)ei;
        s = (int)p[e];
        d = (int)p[N_EDGES + e];
    } else {
        const int* p = (const int*)ei;
        s = p[e];
        d = p[N_EDGES + e];
    }
    int pos = atomicAdd(&g_fill[d], 1);
    g_cw[pos] = make_int2(s, __float_as_int(g_dis[s] * g_dis[d]));
}

__global__ void bn_stats_k(const float* __restrict__ x) {
    int col = threadIdx.x & 127;
    int r = blockIdx.x * 2 + (threadIdx.x >> 7);
    float s = 0.f, q = 0.f;
    for (; r < N_NODES; r += gridDim.x * 2) {
        float v = x[(size_t)r * 128 + col];
        g_x16[(size_t)r * 128 + col] = __float2half_rn(v);
        s += v;
        q += v * v;
    }
    atomicAdd(&g_bnsum[col], s);
    atomicAdd(&g_bnsq[col], q);
}

// BN fold: blocks 0..31 split BN-scaled W1; block 32 folds bias b1' = b1 + t@W1
__global__ void bn_fold_k(const float* __restrict__ gamma, const float* __restrict__ beta,
                          const float* __restrict__ W1, const float* __restrict__ b1,
                          __half* __restrict__ hi, __half* __restrict__ lo) {
    int b = blockIdx.x, t = threadIdx.x;
    if (b < 32) {
        int idx = b * 256 + t;           // < 8192
        int k = idx >> 6, n = idx & 63;
        float mean = g_bnsum[k] * (1.0f / N_NODES);
        float var  = g_bnsq[k] * (1.0f / N_NODES) - mean * mean;
        float s = gamma[k] * rsqrtf(var + 1e-5f);
        float w = W1[idx] * s;
        __half h = __float2half_rn(w);
        hi[n * 128 + k] = h;
        lo[n * 128 + k] = __float2half_rn(w - __half2float(h));
    } else {
        __shared__ float ts[128];
        if (t < 128) {
            float mean = g_bnsum[t] * (1.0f / N_NODES);
            float var  = g_bnsq[t] * (1.0f / N_NODES) - mean * mean;
            float s = gamma[t] * rsqrtf(var + 1e-5f);
            ts[t] = beta[t] - mean * s;
        }
        __syncthreads();
        if (t < 64) {
            float acc = b1[t];
            for (int k = 0; k < 128; k++)
                acc += ts[k] * W1[k * 64 + t];
            g_b1f[t] = acc;
        }
    }
}

// CSR propagation on g_act segments: 4 nodes/warp, 8 lanes x uint4 per row.
__global__ void __launch_bounds__(256) prop_k(const __half* __restrict__ in,
                                              __half* __restrict__ out) {
    int w = blockIdx.x * 8 + (threadIdx.x >> 5);
    int lane = threadIdx.x & 31;
    int node = (w << 2) + (lane >> 3);
    int li = lane & 7;
    int beg = g_rowptr[node], end = g_rowptr[node + 1];
    float a0 = 0.f, a1 = 0.f, a2 = 0.f, a3 = 0.f;
    float a4 = 0.f, a5 = 0.f, a6 = 0.f, a7 = 0.f;
    int e = beg;
    while (__any_sync(0xffffffffu, e < end)) {
#pragma unroll
        for (int u = 0; u < 4; u++) {
            int ee = min(e + u, N_EDGES - 1);
            int2 c = __ldg(g_cw + ee);
            float wv = (e + u < end) ? __int_as_float(c.y) : 0.f;
            uint4 r = __ldg((const uint4*)(in + (size_t)c.x * 256) + li);
            float2 f0 = __half22float2(*(__half2*)&r.x);
            float2 f1 = __half22float2(*(__half2*)&r.y);
            float2 f2 = __half22float2(*(__half2*)&r.z);
            float2 f3 = __half22float2(*(__half2*)&r.w);
            a0 = fmaf(wv, f0.x, a0);
            a1 = fmaf(wv, f0.y, a1);
            a2 = fmaf(wv, f1.x, a2);
            a3 = fmaf(wv, f1.y, a3);
            a4 = fmaf(wv, f2.x, a4);
            a5 = fmaf(wv, f2.y, a5);
            a6 = fmaf(wv, f3.x, a6);
            a7 = fmaf(wv, f3.y, a7);
        }
        e += 4;
    }
    __half2 o0 = __floats2half2_rn(a0, a1);
    __half2 o1 = __floats2half2_rn(a2, a3);
    __half2 o2 = __floats2half2_rn(a4, a5);
    __half2 o3 = __floats2half2_rn(a6, a7);
    uint4 uo = make_uint4(*(uint32_t*)&o0, *(uint32_t*)&o1,
                          *(uint32_t*)&o2, *(uint32_t*)&o3);
    *((uint4*)(out + (size_t)node * 256) + li) = uo;
}

// ---------------- L1 GEMM: h = gelu(x16 @ W1' + b1') -> g_act seg0 ----------------
__global__ void __launch_bounds__(256, 4) tgemm_l1_k(
    const __half* __restrict__ Ag,
    const __half* __restrict__ Whg, const __half* __restrict__ Wlg,
    __half* __restrict__ Cact) {
    __shared__ __half As[2][128][AST];
    __shared__ __half Wh[2][64][AST];
    __shared__ __half Wl[2][64][AST];

    int tid = threadIdx.x;
    int lane = tid & 31, wid = tid >> 5;
    int gid = lane >> 2, tg = lane & 3;
    int warp_m = wid & 3, warp_n = wid >> 2;
    int Rm = warp_m * 32;
    int Cn = warp_n * 32;
    int m0 = blockIdx.x * 128;

    uint32_t asb[2] = { smaddr(&As[0][0][0]), smaddr(&As[1][0][0]) };
    uint32_t whb[2] = { smaddr(&Wh[0][0][0]), smaddr(&Wh[1][0][0]) };
    uint32_t wlb[2] = { smaddr(&Wl[0][0][0]), smaddr(&Wl[1][0][0]) };

    float d[2][4][4];
#pragma unroll
    for (int mt = 0; mt < 2; mt++)
#pragma unroll
        for (int nt = 0; nt < 4; nt++)
#pragma unroll
            for (int q = 0; q < 4; q++) d[mt][nt][q] = 0.f;

    dbgemm<4, true>(d, Ag, m0, 128, 0u, 0, CST, Whg, Wlg, 128, asb, whb, wlb,
                    tid, lane, Rm, Cn);

#pragma unroll
    for (int mt = 0; mt < 2; mt++) {
#pragma unroll
        for (int nt = 0; nt < 4; nt++) {
            int col = Cn + nt * 8 + tg * 2;
            float bx = g_b1f[col], by = g_b1f[col + 1];
            int r0 = m0 + Rm + mt * 16 + gid;
            int r1 = r0 + 8;
            float v0 = gelu_f(d[mt][nt][0] + bx), v1 = gelu_f(d[mt][nt][1] + by);
            float v2 = gelu_f(d[mt][nt][2] + bx), v3 = gelu_f(d[mt][nt][3] + by);
            if (r0 < N_NODES)
                *(__half2*)(Cact + (size_t)r0 * 256 + col) = __floats2half2_rn(v0, v1);
            if (r1 < N_NODES)
                *(__half2*)(Cact + (size_t)r1 * 256 + col) = __floats2half2_rn(v2, v3);
        }
    }
}

// ---------------- fused 2-stage chain (TAG1 + L2) ----------------
// stage1 (hi-only W): Cs = gelu(g_act @ T1 + t1b), N=64
// stage2 (hi-only W): h = gelu(Cs @ W2 + b2) -> g_act seg0 (stride 256)
__global__ void __launch_bounds__(256) chain_k(
    const __half* __restrict__ act,
    const __half* __restrict__ Wahg,
    const float* __restrict__ ba,
    const __half* __restrict__ Wbhg,
    const float* __restrict__ bb,
    __half* __restrict__ C16) {
    constexpr uint32_t WSZ = 64 * AST * 2;   // 5120
    extern __shared__ char sm[];
    uint32_t sbase = smaddr(sm);
    uint32_t asb[2] = { sbase, sbase + 10240 };
    uint32_t cs_a   = sbase + 20480;
    uint32_t wbase  = sbase + 38912;
    uint32_t whb[2] = { wbase, wbase + WSZ };
    uint32_t wlb[2] = { wbase, wbase + WSZ };  // unused (hi-only)
    __half (*Cs)[CST] = (__half(*)[CST])(sm + 20480);

    int tid = threadIdx.x;
    int lane = tid & 31, wid = tid >> 5;
    int gid = lane >> 2, tg = lane & 3;
    int warp_m = wid & 3, warp_n = wid >> 2;
    int Rm = warp_m * 32;
    int Cn = warp_n * 32;
    int m0 = blockIdx.x * 128;

    // -------- stage 1: K=256 from g_act, N=64 --------
    {
        float d[2][4][4];
#pragma unroll
        for (int mt = 0; mt < 2; mt++)
#pragma unroll
            for (int nt = 0; nt < 4; nt++)
#pragma unroll
                for (int q = 0; q < 4; q++) d[mt][nt][q] = 0.f;

        dbgemm<4, false>(d, act, m0, 256, 0u, 0, CST, Wahg, Wahg, 256,
                         asb, whb, wlb, tid, lane, Rm, Cn);

#pragma unroll
        for (int mt = 0; mt < 2; mt++) {
#pragma unroll
            for (int nt = 0; nt < 4; nt++) {
                int col = Cn + nt * 8 + tg * 2;
                float bx = ba[col], by = ba[col + 1];
                int r0 = Rm + mt * 16 + gid;
                *(__half2*)&Cs[r0][col] =
                    __floats2half2_rn(gelu_f(d[mt][nt][0] + bx), gelu_f(d[mt][nt][1] + by));
                *(__half2*)&Cs[r0 + 8][col] =
                    __floats2half2_rn(gelu_f(d[mt][nt][2] + bx), gelu_f(d[mt][nt][3] + by));
            }
        }
    }
    __syncthreads();

    // -------- stage 2: K=64 (Cs), N=64 -> h --------
    {
        float d[2][4][4];
#pragma unroll
        for (int mt = 0; mt < 2; mt++)
#pragma unroll
            for (int nt = 0; nt < 4; nt++)
#pragma unroll
                for (int q = 0; q < 4; q++) d[mt][nt][q] = 0.f;

        dbgemm<4, false>(d, nullptr, m0, 0, cs_a, 64, CST, Wbhg, Wbhg, 64,
                         asb, whb, wlb, tid, lane, Rm, Cn);

#pragma unroll
        for (int mt = 0; mt < 2; mt++) {
#pragma unroll
            for (int nt = 0; nt < 4; nt++) {
                int col = Cn + nt * 8 + tg * 2;
                float bx = bb[col], by = bb[col + 1];
                int r0 = m0 + Rm + mt * 16 + gid;
                int r1 = r0 + 8;
                float v0 = gelu_f(d[mt][nt][0] + bx), v1 = gelu_f(d[mt][nt][1] + by);
                float v2 = gelu_f(d[mt][nt][2] + bx), v3 = gelu_f(d[mt][nt][3] + by);
                if (r0 < N_NODES)
                    *(__half2*)(C16 + (size_t)r0 * 256 + col) = __floats2half2_rn(v0, v1);
                if (r1 < N_NODES)
                    *(__half2*)(C16 + (size_t)r1 * 256 + col) = __floats2half2_rn(v2, v3);
            }
        }
    }
}

// ---------------- fused 3-stage chain (TAG2 + L3 + L4) ----------------
// stage1 (hi-only): Cs1 = gelu(g_act @ T2 + t2b), N=64 (smem)
// stage2 (hi-only): a = gelu(concat(x16, Cs1) @ W3 + b3), N=128 (smem fp16)
// stage3 (hi/lo)  : out = a @ W4 + b4 (fp32 global)
__global__ void __launch_bounds__(256) chain3_k(
    const __half* __restrict__ act,
    const __half* __restrict__ Wahg, const float* __restrict__ ba,
    const __half* __restrict__ xg,
    const __half* __restrict__ Wbhg, const float* __restrict__ bb,
    const __half* __restrict__ Wchg, const __half* __restrict__ Wclg,
    const float* __restrict__ bc,
    float* __restrict__ out) {
    constexpr uint32_t WSZ64  = 64 * AST * 2;    // 5120
    constexpr uint32_t WSZ128 = 128 * AST * 2;   // 10240
    extern __shared__ char sm[];
    uint32_t sbase = smaddr(sm);
    uint32_t asb[2] = { sbase, sbase + 10240 };
    uint32_t cs1_a  = sbase + 20480;
    uint32_t wbase  = sbase + 38912;
    __half (*Cs1)[CST]  = (__half(*)[CST])(sm + 20480);
    __half (*C2)[C2ST]  = (__half(*)[C2ST])(sm);   // overlaps As+Cs1 (34816 <= 38912)
    uint32_t c2_a = sbase;

    int tid = threadIdx.x;
    int lane = tid & 31, wid = tid >> 5;
    int gid = lane >> 2, tg = lane & 3;
    int warp_m = wid & 3, warp_n = wid >> 2;
    int Rm = warp_m * 32;
    int m0 = blockIdx.x * 128;

    // -------- stage 1: K=256 from g_act, N=64, hi-only T2 --------
    {
        uint32_t whb[2] = { wbase, wbase + WSZ64 };
        int Cn = warp_n * 32;
        float d[2][4][4];
#pragma unroll
        for (int mt = 0; mt < 2; mt++)
#pragma unroll
            for (int nt = 0; nt < 4; nt++)
#pragma unroll
                for (int q = 0; q < 4; q++) d[mt][nt][q] = 0.f;

        dbgemm<4, false>(d, act, m0, 256, 0u, 0, CST, Wahg, Wahg, 256,
                         asb, whb, whb, tid, lane, Rm, Cn);

#pragma unroll
        for (int mt = 0; mt < 2; mt++) {
#pragma unroll
            for (int nt = 0; nt < 4; nt++) {
                int col = Cn + nt * 8 + tg * 2;
                float bx = ba[col], by = ba[col + 1];
                int r0 = Rm + mt * 16 + gid;
                *(__half2*)&Cs1[r0][col] =
                    __floats2half2_rn(gelu_f(d[mt][nt][0] + bx), gelu_f(d[mt][nt][1] + by));
                *(__half2*)&Cs1[r0 + 8][col] =
                    __floats2half2_rn(gelu_f(d[mt][nt][2] + bx), gelu_f(d[mt][nt][3] + by));
            }
        }
    }
    __syncthreads();

    // -------- stage 2: K=128 (x16 global) + 64 (Cs1), N=128, hi-only W3 --------
    {
        uint32_t whb[2] = { wbase, wbase + WSZ128 };
        int Cn = warp_n * 64;
        float d[2][8][4];
#pragma unroll
        for (int mt = 0; mt < 2; mt++)
#pragma unroll
            for (int nt = 0; nt < 8; nt++)
#pragma unroll
                for (int q = 0; q < 4; q++) d[mt][nt][q] = 0.f;

        dbgemm<8, false>(d, xg, m0, 128, cs1_a, 64, CST, Wbhg, Wbhg, 192,
                         asb, whb, whb, tid, lane, Rm, Cn);

        // epilogue: gelu -> C2 smem (fp16, stride C2ST). As/Cs1 are dead now.
#pragma unroll
        for (int mt = 0; mt < 2; mt++) {
#pragma unroll
            for (int nt = 0; nt < 8; nt++) {
                int col = Cn + nt * 8 + tg * 2;
                float bx = bb[col], by = bb[col + 1];
                int r0 = Rm + mt * 16 + gid;
                *(__half2*)&C2[r0][col] =
                    __floats2half2_rn(gelu_f(d[mt][nt][0] + bx), gelu_f(d[mt][nt][1] + by));
                *(__half2*)&C2[r0 + 8][col] =
                    __floats2half2_rn(gelu_f(d[mt][nt][2] + bx), gelu_f(d[mt][nt][3] + by));
            }
        }
    }
    __syncthreads();

    // -------- stage 3: K=128 (C2 smem), N=64, W4 hi/lo -> fp32 out --------
    {
        uint32_t whb[2] = { wbase, wbase + 2 * WSZ64 };
        uint32_t wlb[2] = { wbase + WSZ64, wbase + 3 * WSZ64 };
        int Cn = warp_n * 32;
        float d[2][4][4];
#pragma unroll
        for (int mt = 0; mt < 2; mt++)
#pragma unroll
            for (int nt = 0; nt < 4; nt++)
#pragma unroll
                for (int q = 0; q < 4; q++) d[mt][nt][q] = 0.f;

        dbgemm<4, true>(d, nullptr, m0, 0, c2_a, 128, C2ST, Wchg, Wclg, 128,
                        asb, whb, wlb, tid, lane, Rm, Cn);

#pragma unroll
        for (int mt = 0; mt < 2; mt++) {
#pragma unroll
            for (int nt = 0; nt < 4; nt++) {
                int col = Cn + nt * 8 + tg * 2;
                float bx = bc[col], by = bc[col + 1];
                int r0 = m0 + Rm + mt * 16 + gid;
                int r1 = r0 + 8;
                if (r0 < N_NODES)
                    *(float2*)(out + (size_t)r0 * 64 + col) =
                        make_float2(d[mt][nt][0] + bx, d[mt][nt][1] + by);
                if (r1 < N_NODES)
                    *(float2*)(out + (size_t)r1 * 64 + col) =
                        make_float2(d[mt][nt][2] + bx, d[mt][nt][3] + by);
            }
        }
    }
}

// ---------------- host launcher ----------------
extern "C" void kernel_launch(void* const* d_in, const int* in_sizes, int n_in,
                              void* d_out, int out_size) {
    const float* x     = (const float*)d_in[0];
    const void*  ei    = d_in[1];
    const float* gamma = (const float*)d_in[2];
    const float* beta  = (const float*)d_in[3];
    const float* W1 = (const float*)d_in[4];  const float* b1  = (const float*)d_in[5];
    const float* T1 = (const float*)d_in[6];  const float* t1b = (const float*)d_in[7];
    const float* W2 = (const float*)d_in[8];  const float* b2  = (const float*)d_in[9];
    const float* T2 = (const float*)d_in[10]; const float* t2b = (const float*)d_in[11];
    const float* W3 = (const float*)d_in[12]; const float* b3  = (const float*)d_in[13];
    const float* W4 = (const float*)d_in[14]; const float* b4  = (const float*)d_in[15];
    float* out = (float*)d_out;

    __half *x16, *act, *wthi, *wtlo;
    cudaGetSymbolAddress((void**)&x16,  g_x16);
    cudaGetSymbolAddress((void**)&act,  g_act);
    cudaGetSymbolAddress((void**)&wthi, g_wthi);
    cudaGetSymbolAddress((void**)&wtlo, g_wtlo);

    const int OT1 = 8192, OW2 = 24576, OT2 = 28672, OW3 = 45056, OW4 = 69632;

    const int EB = (N_EDGES + 255) / 256;
    const int NB = (N_NODES + 255) / 256;   // 391
    const int GB = (N_NODES + 127) / 128;   // 782
    const int PB = N_NODES / 32;            // 3125 (4 nodes/warp, 8 warps/block)

    const int SM_C1 = 38912 + 2 * 64  * AST * 2;  // 49152
    const int SM_C3 = 38912 + 2 * 128 * AST * 2;  // 59392
    cudaFuncSetAttribute((const void*)chain_k,
                         cudaFuncAttributeMaxDynamicSharedMemorySize, SM_C1);
    cudaFuncSetAttribute((const void*)chain3_k,
                         cudaFuncAttributeMaxDynamicSharedMemorySize, SM_C3);

    // fork: weights/BN/L1 on s1, graph preprocessing on stream 0
    cudaStream_t s1;
    cudaStreamCreateWithFlags(&s1, cudaStreamNonBlocking);
    cudaEvent_t e0, e1;
    cudaEventCreateWithFlags(&e0, cudaEventDisableTiming);
    cudaEventCreateWithFlags(&e1, cudaEventDisableTiming);
    cudaEventRecord(e0, 0);
    cudaStreamWaitEvent(s1, e0, 0);

    // ---- stream s1: weight pre-split + BN zero, BN stats, BN fold, L1 GEMM ----
    prepw_all_k<<<305, 256, 0, s1>>>(T1, W2, T2, W3, W4, wthi, wtlo);
    bn_stats_k<<<512, 256, 0, s1>>>(x);
    bn_fold_k<<<33, 256, 0, s1>>>(gamma, beta, W1, b1, wthi, wtlo);
    tgemm_l1_k<<<GB, 256, 0, s1>>>(x16, wthi, wtlo, act);
    cudaEventRecord(e1, s1);

    // ---- stream 0: graph preprocessing ----
    zero_detect_k<<<NB, 256>>>((const int*)ei);
    deg_k<<<EB, 256>>>(ei);
    blkred_dis_k<<<NB, 256>>>();
    partscan_k<<<1, 512>>>(NB);
    blkscan_k<<<NB, 256>>>();
    csrfill_k<<<EB, 256>>>(ei);

    cudaStreamWaitEvent(0, e1, 0);   // join: props need CSR + h

    // ---- TAGConv1: props fill segs 1..3, then chain (TAG1 + L2) -> h in seg0 ----
    prop_k<<<PB, 256>>>(act,       act + 64);
    prop_k<<<PB, 256>>>(act + 64,  act + 128);
    prop_k<<<PB, 256>>>(act + 128, act + 192);
    chain_k<<<GB, 256, SM_C1>>>(
        act, wthi + OT1, t1b, wthi + OW2, b2, act);

    // ---- TAGConv2: props, then 3-stage chain (TAG2 + L3 + L4) -> out ----
    prop_k<<<PB, 256>>>(act,       act + 64);
    prop_k<<<PB, 256>>>(act + 64,  act + 128);
    prop_k<<<PB, 256>>>(act + 128, act + 192);
    chain3_k<<<GB, 256, SM_C3>>>(
        act, wthi + OT2, t2b, x16, wthi + OW3, b3,
        wthi + OW4, wtlo + OW4, b4, out);
}